// round 7
// baseline (speedup 1.0000x reference)
#include <cuda_runtime.h>
#include <cuda_bf16.h>
#include <math.h>
#include <cstdint>

#define BB 32
#define SS 2048
#define FF 128
#define DK 32
#define NROWS (BB*SS)

// Packed projections, 64 bf16 per row (128B): [hi(32) | lo(32)]
// q pre-scaled by log2(e)/sqrt(32)  (scores in log2 domain -> ex2)
__device__ __nv_bfloat16 g_qp[NROWS*64];
__device__ __nv_bfloat16 g_kp[NROWS*64];
__device__ float g_vw[NROWS*4];            // v_in @ (Wv @ Wo_eff), padded to 4
__device__ float4 g_part[2*NROWS];         // split-K partials {l, A0, A1, A2}

static __device__ __forceinline__ uint32_t smem_u32(const void* p) {
    uint32_t a;
    asm("{ .reg .u64 t; cvta.to.shared.u64 t, %1; cvt.u32.u64 %0, t; }" : "=r"(a) : "l"(p));
    return a;
}
static __device__ __forceinline__ void cp16(uint32_t dst, const void* src) {
    asm volatile("cp.async.cg.shared.global [%0], [%1], 16;" :: "r"(dst), "l"(src) : "memory");
}
#define CP_COMMIT() asm volatile("cp.async.commit_group;" ::: "memory")
#define CP_WAIT(n)  asm volatile("cp.async.wait_group %0;" :: "n"(n) : "memory")

static __device__ __forceinline__ float ex2f(float x) {
    float y; asm("ex2.approx.f32 %0, %1;" : "=f"(y) : "f"(x)); return y;
}

#define LDSM_X4(r0,r1,r2,r3,addr) \
    asm volatile("ldmatrix.sync.aligned.m8n8.x4.shared.b16 {%0,%1,%2,%3}, [%4];" \
        : "=r"(r0), "=r"(r1), "=r"(r2), "=r"(r3) : "r"(addr))

#define MMA16816(c0,c1,c2,c3,a0,a1,a2,a3,b0,b1) \
    asm volatile("mma.sync.aligned.m16n8k16.row.col.f32.bf16.bf16.f32 " \
        "{%0,%1,%2,%3}, {%4,%5,%6,%7}, {%8,%9}, {%0,%1,%2,%3};" \
        : "+f"(c0), "+f"(c1), "+f"(c2), "+f"(c3) \
        : "r"(a0), "r"(a1), "r"(a2), "r"(a3), "r"(b0), "r"(b1))

// ---------------------------------------------------------------------------
// Projection: grid (512, 3), 128 threads. Each block streams 128 rows in
// 4 chunks of 32 (cp.async double-buffered). 8 rows/thread register-blocked,
// transposed weights (stride 132) for float4 w-loads.
// ---------------------------------------------------------------------------
#define PJ_WT_OFF 0
#define PJ_BUF_OFF 16896
#define PJ_SMEM (PJ_BUF_OFF + 2*16384)    // 49664

__global__ __launch_bounds__(128) void proj3_kernel(
    const float* __restrict__ qin, const float* __restrict__ kin, const float* __restrict__ vin,
    const float* __restrict__ Wq, const float* __restrict__ bq,
    const float* __restrict__ Wk, const float* __restrict__ bk,
    const float* __restrict__ Wv, const float* __restrict__ Wo) {
    extern __shared__ __align__(16) unsigned char dsm[];
    float* sWT = (float*)(dsm + PJ_WT_OFF);      // [32][132] transposed W
    const int tid  = threadIdx.x;
    const int lane = tid & 31;
    const int wr   = tid >> 5;
    const int phase = blockIdx.y;
    const size_t row0 = (size_t)blockIdx.x * 128;
    const uint32_t b0 = smem_u32(dsm + PJ_BUF_OFF);
    const uint32_t b1 = smem_u32(dsm + PJ_BUF_OFF + 16384);

    if (phase < 2) {
        const float* W  = phase ? Wk : Wq;
        const float* bb = phase ? bk : bq;
        const float* in = phase ? kin : qin;
        __nv_bfloat16* gout = phase ? g_kp : g_qp;

        // transposed weight load
        for (int i = tid; i < FF*DK; i += 128) {
            int f = i >> 5, c = i & 31;
            sWT[c*132 + f] = W[i];
        }
        // prologue: chunk 0
        #pragma unroll
        for (int k = 0; k < 8; ++k) {
            int i = tid + k*128;
            cp16(b0 + i*16, (const float4*)in + row0*32 + i);
        }
        CP_COMMIT();

        const float bias = bb[lane];
        const float qs = phase ? 1.0f
                               : 0.17677669529663687f * 1.4426950408889634f;
        #pragma unroll 1
        for (int c = 0; c < 4; ++c) {
            if (c < 3) {
                uint32_t db = ((c+1) & 1) ? b1 : b0;
                #pragma unroll
                for (int k = 0; k < 8; ++k) {
                    int i = tid + k*128;
                    cp16(db + i*16, (const float4*)in + (row0 + (c+1)*32)*32 + i);
                }
                CP_COMMIT();
                CP_WAIT(1);
            } else {
                CP_WAIT(0);
            }
            __syncthreads();

            const float* buf = (const float*)(dsm + PJ_BUF_OFF + (c & 1)*16384);
            const int r0r = wr*8;
            float acc[8];
            #pragma unroll
            for (int r = 0; r < 8; ++r) acc[r] = 0.f;

            #pragma unroll 2
            for (int f = 0; f < FF; f += 4) {
                float4 w4 = *(float4*)&sWT[lane*132 + f];
                #pragma unroll
                for (int r = 0; r < 8; ++r) {
                    float4 x = *(const float4*)&buf[(r0r + r)*FF + f];
                    acc[r] = fmaf(x.x, w4.x, fmaf(x.y, w4.y,
                             fmaf(x.z, w4.z, fmaf(x.w, w4.w, acc[r]))));
                }
            }
            #pragma unroll
            for (int r = 0; r < 8; ++r) {
                float v = (acc[r] + bias) * qs;
                __nv_bfloat16 h  = __float2bfloat16(v);
                __nv_bfloat16 lo = __float2bfloat16(v - __bfloat162float(h));
                size_t rr = row0 + c*32 + r0r + r;
                gout[rr*64 + lane]      = h;
                gout[rr*64 + 32 + lane] = lo;
            }
            __syncthreads();
        }
    } else {
        // VW: v_in @ (Wv @ Wo_eff)
        float* sWv  = sWT;                 // [FF*3]
        float* sWoE = sWT + 384;           // [DK*3]
        if (tid < 96) {
            int d = tid / 3, f = tid - d*3;
            float s = 0.f;
            #pragma unroll
            for (int h = 0; h < 16; ++h) s += Wo[(h*DK + d)*3 + f];
            sWoE[tid] = s;
        }
        #pragma unroll
        for (int k = 0; k < 8; ++k) {
            int i = tid + k*128;
            cp16(b0 + i*16, (const float4*)vin + row0*32 + i);
        }
        CP_COMMIT();
        __syncthreads();
        for (int i = tid; i < FF*3; i += 128) {
            int r = i / 3, f = i - r*3;
            float s = 0.f;
            #pragma unroll
            for (int d = 0; d < DK; ++d) s = fmaf(Wv[r*DK + d], sWoE[d*3 + f], s);
            sWv[i] = s;
        }
        __syncthreads();

        #pragma unroll 1
        for (int c = 0; c < 4; ++c) {
            if (c < 3) {
                uint32_t db = ((c+1) & 1) ? b1 : b0;
                #pragma unroll
                for (int k = 0; k < 8; ++k) {
                    int i = tid + k*128;
                    cp16(db + i*16, (const float4*)vin + (row0 + (c+1)*32)*32 + i);
                }
                CP_COMMIT();
                CP_WAIT(1);
            } else {
                CP_WAIT(0);
            }
            __syncthreads();
            if (tid < 96) {
                const float* buf = (const float*)(dsm + PJ_BUF_OFF + (c & 1)*16384);
                int r = tid / 3, f = tid - r*3;
                float s0=0.f,s1=0.f,s2=0.f,s3=0.f;
                #pragma unroll 8
                for (int ff = 0; ff < FF; ff += 4) {
                    s0 = fmaf(buf[r*FF+ff+0], sWv[(ff+0)*3+f], s0);
                    s1 = fmaf(buf[r*FF+ff+1], sWv[(ff+1)*3+f], s1);
                    s2 = fmaf(buf[r*FF+ff+2], sWv[(ff+2)*3+f], s2);
                    s3 = fmaf(buf[r*FF+ff+3], sWv[(ff+3)*3+f], s3);
                }
                g_vw[(row0 + c*32 + r)*4 + f] = (s0+s1)+(s2+s3);
            }
            __syncthreads();
        }
    }
}

// ---------------------------------------------------------------------------
// Flash kernel: 256 threads (8 warps x 32 q-rows), q-tile 256, split-K 2-way.
// cp.async double-buffered K tiles with vw in row padding. Writes float4
// partials {l, A0, A1, A2} per q-row; finalize kernel combines.
// ---------------------------------------------------------------------------
#define RSTR 144
#define KTILEB (128*RSTR)              // 18432
#define SQ_OFF 0
#define SK_OFF (256*RSTR)              // 36864
#define SMEM_BYTES (SK_OFF + 2*KTILEB) // 73728

__global__ __launch_bounds__(256, 3)
void flash7_kernel(void) {
    extern __shared__ __align__(16) unsigned char smem[];
    const int tid  = threadIdx.x;
    const int wid  = tid >> 5, lane = tid & 31;
    const size_t base = (size_t)blockIdx.y * SS;
    const int q0 = blockIdx.x * 256;
    const int z  = blockIdx.z;           // key half
    const uint32_t sbase = smem_u32(smem);

    // prologue: Q tile (group 0), first K tile (group 1)
    #pragma unroll
    for (int k = 0; k < 8; ++k) {
        int i = tid + k*256;
        int rr = i >> 3, sg = i & 7;
        cp16(sbase + SQ_OFF + rr*RSTR + sg*16,
             (const unsigned char*)g_qp + (base + q0 + rr)*128 + sg*16);
    }
    CP_COMMIT();
    {
        const size_t kb = base + (size_t)z * 1024;
        #pragma unroll
        for (int k = 0; k < 4; ++k) {
            int i = tid + k*256;
            int rr = i >> 3, sg = i & 7;
            cp16(sbase + SK_OFF + rr*RSTR + sg*16,
                 (const unsigned char*)g_kp + (kb + rr)*128 + sg*16);
        }
        if (tid < 128)
            cp16(sbase + SK_OFF + tid*RSTR + 128, g_vw + (kb + tid)*4);
    }
    CP_COMMIT();
    CP_WAIT(1);            // Q ready
    __syncthreads();

    const int lr  = lane & 7;
    const int sel = lane >> 3;

    // A fragments (loop-invariant): qh steps {0,1} then ql steps {0,1}
    uint32_t aF[2][4][4];
    #pragma unroll
    for (int mt = 0; mt < 2; ++mt) {
        int arow = wid*32 + mt*16 + lr + (sel & 1)*8;
        uint32_t abase = sbase + SQ_OFF + arow*RSTR + (sel >> 1)*16;
        #pragma unroll
        for (int g = 0; g < 4; ++g)
            LDSM_X4(aF[mt][g][0], aF[mt][g][1], aF[mt][g][2], aF[mt][g][3], abase + g*32);
    }

    float l[2][2], Ax[2][2], Ay[2][2], Az[2][2];
    #pragma unroll
    for (int mt = 0; mt < 2; ++mt)
        #pragma unroll
        for (int hf = 0; hf < 2; ++hf) {
            l[mt][hf] = 0.f; Ax[mt][hf] = 0.f; Ay[mt][hf] = 0.f; Az[mt][hf] = 0.f;
        }
    const int qc = (lane & 3)*2;

    #pragma unroll 1
    for (int ti = 0; ti < 8; ++ti) {
        if (ti < 7) {
            const size_t kb = base + (size_t)z*1024 + (size_t)(ti+1)*128;
            uint32_t db = sbase + SK_OFF + ((ti+1) & 1)*KTILEB;
            #pragma unroll
            for (int k = 0; k < 4; ++k) {
                int i = tid + k*256;
                int rr = i >> 3, sg = i & 7;
                cp16(db + rr*RSTR + sg*16,
                     (const unsigned char*)g_kp + (kb + rr)*128 + sg*16);
            }
            if (tid < 128)
                cp16(db + tid*RSTR + 128, g_vw + (kb + tid)*4);
            CP_COMMIT();
            CP_WAIT(1);
        } else {
            CP_WAIT(0);
        }
        __syncthreads();

        const uint32_t skoff = SK_OFF + (ti & 1)*KTILEB;
        const uint32_t sk = sbase + skoff;
        #pragma unroll 4
        for (int j = 0; j < 16; ++j) {
            uint32_t bbase = sk + (j*8 + lr)*RSTR + sel*16;
            uint32_t bF[8];
            LDSM_X4(bF[0], bF[1], bF[2], bF[3], bbase);        // kh steps 0,1
            LDSM_X4(bF[4], bF[5], bF[6], bF[7], bbase + 64);   // kl steps 0,1

            float4 va = *(float4*)(smem + skoff + (j*8 + qc)*RSTR + 128);
            float4 vb = *(float4*)(smem + skoff + (j*8 + qc + 1)*RSTR + 128);

            #pragma unroll
            for (int mt = 0; mt < 2; ++mt) {
                float cA0=0.f, cA1=0.f, cA2=0.f, cA3=0.f;
                float cB0=0.f, cB1=0.f, cB2=0.f, cB3=0.f;
                MMA16816(cA0,cA1,cA2,cA3, aF[mt][0][0],aF[mt][0][1],aF[mt][0][2],aF[mt][0][3], bF[0],bF[1]);
                MMA16816(cB0,cB1,cB2,cB3, aF[mt][1][0],aF[mt][1][1],aF[mt][1][2],aF[mt][1][3], bF[2],bF[3]);
                MMA16816(cA0,cA1,cA2,cA3, aF[mt][0][0],aF[mt][0][1],aF[mt][0][2],aF[mt][0][3], bF[4],bF[5]);
                MMA16816(cB0,cB1,cB2,cB3, aF[mt][1][0],aF[mt][1][1],aF[mt][1][2],aF[mt][1][3], bF[6],bF[7]);
                MMA16816(cA0,cA1,cA2,cA3, aF[mt][2][0],aF[mt][2][1],aF[mt][2][2],aF[mt][2][3], bF[0],bF[1]);
                MMA16816(cB0,cB1,cB2,cB3, aF[mt][3][0],aF[mt][3][1],aF[mt][3][2],aF[mt][3][3], bF[2],bF[3]);

                float p0 = ex2f(cA0 + cB0), p1 = ex2f(cA1 + cB1);
                float p2 = ex2f(cA2 + cB2), p3 = ex2f(cA3 + cB3);
                l[mt][0] += p0 + p1;  l[mt][1] += p2 + p3;
                Ax[mt][0] = fmaf(p0, va.x, fmaf(p1, vb.x, Ax[mt][0]));
                Ay[mt][0] = fmaf(p0, va.y, fmaf(p1, vb.y, Ay[mt][0]));
                Az[mt][0] = fmaf(p0, va.z, fmaf(p1, vb.z, Az[mt][0]));
                Ax[mt][1] = fmaf(p2, va.x, fmaf(p3, vb.x, Ax[mt][1]));
                Ay[mt][1] = fmaf(p2, va.y, fmaf(p3, vb.y, Ay[mt][1]));
                Az[mt][1] = fmaf(p2, va.z, fmaf(p3, vb.z, Az[mt][1]));
            }
        }
        __syncthreads();
    }

    // quad-reduce and write partials
    #pragma unroll
    for (int mt = 0; mt < 2; ++mt)
        #pragma unroll
        for (int hf = 0; hf < 2; ++hf) {
            #pragma unroll
            for (int o = 1; o <= 2; o <<= 1) {
                l[mt][hf]  += __shfl_xor_sync(0xffffffffu, l[mt][hf],  o);
                Ax[mt][hf] += __shfl_xor_sync(0xffffffffu, Ax[mt][hf], o);
                Ay[mt][hf] += __shfl_xor_sync(0xffffffffu, Ay[mt][hf], o);
                Az[mt][hf] += __shfl_xor_sync(0xffffffffu, Az[mt][hf], o);
            }
        }
    if ((lane & 3) == 0) {
        #pragma unroll
        for (int mt = 0; mt < 2; ++mt)
            #pragma unroll
            for (int hf = 0; hf < 2; ++hf) {
                size_t r = base + q0 + wid*32 + mt*16 + (lane >> 2) + hf*8;
                g_part[(size_t)z*NROWS + r] =
                    make_float4(l[mt][hf], Ax[mt][hf], Ay[mt][hf], Az[mt][hf]);
            }
    }
}

// ---------------------------------------------------------------------------
// Finalize: combine 2 split-K partials, normalize, add constant.
// ---------------------------------------------------------------------------
__global__ __launch_bounds__(256) void finalize_kernel(
    float* __restrict__ out,
    const float* __restrict__ bv,
    const float* __restrict__ Wo,
    const float* __restrict__ bo) {
    __shared__ float sCST[3];
    const int tid = threadIdx.x;
    if (tid < 3) {
        float s = bo[tid];
        #pragma unroll
        for (int d = 0; d < DK; ++d) {
            float w = 0.f;
            #pragma unroll
            for (int h = 0; h < 16; ++h) w += Wo[(h*DK + d)*3 + tid];
            s = fmaf(bv[d], w, s);
        }
        sCST[tid] = s;
    }
    __syncthreads();
    size_t row = (size_t)blockIdx.x * 256 + tid;
    float4 p0 = g_part[row];
    float4 p1 = g_part[NROWS + row];
    float inv = 1.0f / (p0.x + p1.x);
    out[row*3 + 0] = fmaf(p0.y + p1.y, inv, sCST[0]);
    out[row*3 + 1] = fmaf(p0.z + p1.z, inv, sCST[1]);
    out[row*3 + 2] = fmaf(p0.w + p1.w, inv, sCST[2]);
}

extern "C" void kernel_launch(void* const* d_in, const int* in_sizes, int n_in,
                              void* d_out, int out_size) {
    const float* qin = (const float*)d_in[0];
    const float* kin = (const float*)d_in[1];
    const float* vin = (const float*)d_in[2];
    const float* Wq  = (const float*)d_in[3];
    const float* bq  = (const float*)d_in[4];
    const float* Wk  = (const float*)d_in[5];
    const float* bk  = (const float*)d_in[6];
    const float* Wv  = (const float*)d_in[7];
    const float* bv  = (const float*)d_in[8];
    const float* Wo  = (const float*)d_in[9];
    const float* bo  = (const float*)d_in[10];
    float* out = (float*)d_out;

    cudaFuncSetAttribute(flash7_kernel,
                         cudaFuncAttributeMaxDynamicSharedMemorySize, SMEM_BYTES);
    cudaFuncSetAttribute(proj3_kernel,
                         cudaFuncAttributeMaxDynamicSharedMemorySize, PJ_SMEM);
    proj3_kernel<<<dim3(NROWS/128, 3), 128, PJ_SMEM>>>(qin, kin, vin, Wq, bq, Wk, bk, Wv, Wo);
    flash7_kernel<<<dim3(SS/256, BB, 2), 256, SMEM_BYTES>>>();
    finalize_kernel<<<NROWS/256, 256>>>(out, bv, Wo, bo);
}

// round 9
// speedup vs baseline: 1.2352x; 1.2352x over previous
#include <cuda_runtime.h>
#include <cuda_bf16.h>
#include <math.h>
#include <cstdint>

#define BB 32
#define SS 2048
#define FF 128
#define DK 32
#define NROWS (BB*SS)

// Packed projections, 64 bf16 per row (128B): [hi(32) | lo(32)]
// q pre-scaled by log2(e)/sqrt(32)  (scores in log2 domain -> ex2)
__device__ __nv_bfloat16 g_qp[NROWS*64];
__device__ __nv_bfloat16 g_kp[NROWS*64];
// PV B-operand, pre-packed bf16x2: per key-pair p, 8 cols g:
//   g<3: {lo=vw[2p][g], hi=vw[2p+1][g]}, g==3: {1,1}, g>3: 0
__device__ uint32_t g_vwp[(NROWS/2)*8];
__device__ float4 g_part[2*NROWS];         // split-K partials {l, A0, A1, A2}

static __device__ __forceinline__ uint32_t smem_u32(const void* p) {
    uint32_t a;
    asm("{ .reg .u64 t; cvta.to.shared.u64 t, %1; cvt.u32.u64 %0, t; }" : "=r"(a) : "l"(p));
    return a;
}
static __device__ __forceinline__ void cp16(uint32_t dst, const void* src) {
    asm volatile("cp.async.cg.shared.global [%0], [%1], 16;" :: "r"(dst), "l"(src) : "memory");
}
#define CP_COMMIT() asm volatile("cp.async.commit_group;" ::: "memory")
#define CP_WAIT(n)  asm volatile("cp.async.wait_group %0;" :: "n"(n) : "memory")

static __device__ __forceinline__ float ex2f(float x) {
    float y; asm("ex2.approx.f32 %0, %1;" : "=f"(y) : "f"(x)); return y;
}
// pack {lo, hi} floats -> bf16x2 (first PTX source goes to upper half)
static __device__ __forceinline__ uint32_t pkbf(float lo, float hi) {
    uint32_t r;
    asm("cvt.rn.bf16x2.f32 %0, %1, %2;" : "=r"(r) : "f"(hi), "f"(lo));
    return r;
}

#define LDSM_X4(r0,r1,r2,r3,addr) \
    asm volatile("ldmatrix.sync.aligned.m8n8.x4.shared.b16 {%0,%1,%2,%3}, [%4];" \
        : "=r"(r0), "=r"(r1), "=r"(r2), "=r"(r3) : "r"(addr))

#define MMA16816(c0,c1,c2,c3,a0,a1,a2,a3,b0,b1) \
    asm volatile("mma.sync.aligned.m16n8k16.row.col.f32.bf16.bf16.f32 " \
        "{%0,%1,%2,%3}, {%4,%5,%6,%7}, {%8,%9}, {%0,%1,%2,%3};" \
        : "+f"(c0), "+f"(c1), "+f"(c2), "+f"(c3) \
        : "r"(a0), "r"(a1), "r"(a2), "r"(a3), "r"(b0), "r"(b1))

// ---------------------------------------------------------------------------
// Projection: grid (512, 3), 128 threads, 128 rows/block in 4 chunks of 32,
// cp.async double-buffered. Conflict-free scalar-broadcast weight layout.
// phase 2 additionally emits g_vwp (packed PV fragments).
// ---------------------------------------------------------------------------
#define PJ_W_OFF 0
#define PJ_BUF_OFF 16384
#define PJ_VS_OFF (PJ_BUF_OFF + 2*16384)
#define PJ_SMEM (PJ_VS_OFF + 512)         // 49664

__global__ __launch_bounds__(128) void proj4_kernel(
    const float* __restrict__ qin, const float* __restrict__ kin, const float* __restrict__ vin,
    const float* __restrict__ Wq, const float* __restrict__ bq,
    const float* __restrict__ Wk, const float* __restrict__ bk,
    const float* __restrict__ Wv, const float* __restrict__ Wo) {
    extern __shared__ __align__(16) unsigned char dsm[];
    float* sW = (float*)(dsm + PJ_W_OFF);        // [FF][DK] row-major
    float* sVS = (float*)(dsm + PJ_VS_OFF);      // vw staging [32][4]
    const int tid  = threadIdx.x;
    const int lane = tid & 31;
    const int wr   = tid >> 5;
    const int phase = blockIdx.y;
    const size_t row0 = (size_t)blockIdx.x * 128;
    const uint32_t b0a = smem_u32(dsm + PJ_BUF_OFF);
    const uint32_t b1a = smem_u32(dsm + PJ_BUF_OFF + 16384);

    if (phase < 2) {
        const float* W  = phase ? Wk : Wq;
        const float* bb = phase ? bk : bq;
        const float* in = phase ? kin : qin;
        __nv_bfloat16* gout = phase ? g_kp : g_qp;

        for (int i = tid; i < FF*DK; i += 128) sW[i] = W[i];
        #pragma unroll
        for (int k = 0; k < 8; ++k) {
            int i = tid + k*128;
            cp16(b0a + i*16, (const float4*)in + row0*32 + i);
        }
        CP_COMMIT();

        const float bias = bb[lane];
        const float qs = phase ? 1.0f
                               : 0.17677669529663687f * 1.4426950408889634f;
        #pragma unroll 1
        for (int c = 0; c < 4; ++c) {
            if (c < 3) {
                uint32_t db = ((c+1) & 1) ? b1a : b0a;
                #pragma unroll
                for (int k = 0; k < 8; ++k) {
                    int i = tid + k*128;
                    cp16(db + i*16, (const float4*)in + (row0 + (c+1)*32)*32 + i);
                }
                CP_COMMIT();
                CP_WAIT(1);
            } else {
                CP_WAIT(0);
            }
            __syncthreads();

            const float* buf = (const float*)(dsm + PJ_BUF_OFF + (c & 1)*16384);
            const int r0r = wr*8;
            float acc[8];
            #pragma unroll
            for (int r = 0; r < 8; ++r) acc[r] = 0.f;

            #pragma unroll 2
            for (int f = 0; f < FF; f += 4) {
                float w0 = sW[(f+0)*DK + lane];
                float w1 = sW[(f+1)*DK + lane];
                float w2 = sW[(f+2)*DK + lane];
                float w3 = sW[(f+3)*DK + lane];
                #pragma unroll
                for (int r = 0; r < 8; ++r) {
                    float4 x = *(const float4*)&buf[(r0r + r)*FF + f];
                    acc[r] = fmaf(x.x, w0, fmaf(x.y, w1,
                             fmaf(x.z, w2, fmaf(x.w, w3, acc[r]))));
                }
            }
            #pragma unroll
            for (int r = 0; r < 8; ++r) {
                float v = (acc[r] + bias) * qs;
                __nv_bfloat16 h  = __float2bfloat16(v);
                __nv_bfloat16 lo = __float2bfloat16(v - __bfloat162float(h));
                size_t rr = row0 + c*32 + r0r + r;
                gout[rr*64 + lane]      = h;
                gout[rr*64 + 32 + lane] = lo;
            }
            __syncthreads();
        }
    } else {
        // VW: vw = v_in @ (Wv @ Wo_eff); emit packed bf16x2 fragments
        float* sWv  = sW;                  // [FF*3]
        float* sWoE = sW + 384;            // [DK*3]
        if (tid < 96) {
            int d = tid / 3, f = tid - d*3;
            float s = 0.f;
            #pragma unroll
            for (int h = 0; h < 16; ++h) s += Wo[(h*DK + d)*3 + f];
            sWoE[tid] = s;
        }
        #pragma unroll
        for (int k = 0; k < 8; ++k) {
            int i = tid + k*128;
            cp16(b0a + i*16, (const float4*)vin + row0*32 + i);
        }
        CP_COMMIT();
        __syncthreads();
        for (int i = tid; i < FF*3; i += 128) {
            int r = i / 3, f = i - r*3;
            float s = 0.f;
            #pragma unroll
            for (int d = 0; d < DK; ++d) s = fmaf(Wv[r*DK + d], sWoE[d*3 + f], s);
            sWv[i] = s;
        }
        __syncthreads();

        #pragma unroll 1
        for (int c = 0; c < 4; ++c) {
            if (c < 3) {
                uint32_t db = ((c+1) & 1) ? b1a : b0a;
                #pragma unroll
                for (int k = 0; k < 8; ++k) {
                    int i = tid + k*128;
                    cp16(db + i*16, (const float4*)vin + (row0 + (c+1)*32)*32 + i);
                }
                CP_COMMIT();
                CP_WAIT(1);
            } else {
                CP_WAIT(0);
            }
            __syncthreads();
            if (tid < 96) {
                const float* buf = (const float*)(dsm + PJ_BUF_OFF + (c & 1)*16384);
                int r = tid / 3, f = tid - r*3;
                float s0=0.f,s1=0.f,s2=0.f,s3=0.f;
                #pragma unroll 8
                for (int ff = 0; ff < FF; ff += 4) {
                    s0 = fmaf(buf[r*FF+ff+0], sWv[(ff+0)*3+f], s0);
                    s1 = fmaf(buf[r*FF+ff+1], sWv[(ff+1)*3+f], s1);
                    s2 = fmaf(buf[r*FF+ff+2], sWv[(ff+2)*3+f], s2);
                    s3 = fmaf(buf[r*FF+ff+3], sWv[(ff+3)*3+f], s3);
                }
                sVS[r*4 + f] = (s0+s1)+(s2+s3);
            }
            __syncthreads();
            // pack: 16 pairs x 8 cols = 128 words
            {
                int p = tid >> 3, g = tid & 7;
                uint32_t w;
                if (g < 3)      w = pkbf(sVS[(2*p)*4 + g], sVS[(2*p+1)*4 + g]);
                else if (g == 3) w = 0x3F803F80u;       // {1.0bf, 1.0bf}
                else             w = 0u;
                g_vwp[((row0 + c*32) >> 1) * 8 + p*8 + g] = w;
            }
            __syncthreads();
        }
    }
}

// ---------------------------------------------------------------------------
// Flash kernel: 256 threads (8 warps x 32 q-rows), q-tile 256, split-K 2-way.
// QK^T via bf16-split HMMA; softmax (no max) via ex2; PV via HMMA with
// pre-packed vwp B-fragments (col 3 = ones -> l accumulated by the MMA).
// ---------------------------------------------------------------------------
#define RSTRK 144
#define SQ_OFF 0
#define SK_OFF 32768                       // Q: 256*128
#define KTILEB (128*RSTRK)                 // 18432
#define VWP_OFF (SK_OFF + 2*KTILEB)        // 69632
#define VWPB 2048
#define SMEM_BYTES (VWP_OFF + 2*VWPB)      // 73728

__global__ __launch_bounds__(256, 3)
void flash8_kernel(void) {
    extern __shared__ __align__(16) unsigned char smem[];
    const int tid  = threadIdx.x;
    const int wid  = tid >> 5, lane = tid & 31;
    const size_t base = (size_t)blockIdx.y * SS;
    const int q0 = blockIdx.x * 256;
    const int z  = blockIdx.z;
    const uint32_t sbase = smem_u32(smem);

    // prologue: Q tile (group 0), first K tile + vwp (group 1)
    #pragma unroll
    for (int k = 0; k < 8; ++k) {
        int i = tid + k*256;
        cp16(sbase + SQ_OFF + i*16,
             (const unsigned char*)g_qp + (base + q0)*128 + i*16);
    }
    CP_COMMIT();
    {
        const size_t kb = base + (size_t)z * 1024;
        #pragma unroll
        for (int k = 0; k < 4; ++k) {
            int i = tid + k*256;
            int rr = i >> 3, sg = i & 7;
            cp16(sbase + SK_OFF + rr*RSTRK + sg*16,
                 (const unsigned char*)g_kp + (kb + rr)*128 + sg*16);
        }
        if (tid < 128)
            cp16(sbase + VWP_OFF + tid*16, g_vwp + (kb >> 1)*8 + tid*4);
    }
    CP_COMMIT();
    CP_WAIT(1);            // Q ready
    __syncthreads();

    const int lr  = lane & 7;
    const int sel = lane >> 3;

    // A fragments (loop-invariant): qh steps {0,1} then ql steps {0,1}
    uint32_t aF[2][4][4];
    #pragma unroll
    for (int mt = 0; mt < 2; ++mt) {
        int arow = wid*32 + mt*16 + lr + (sel & 1)*8;
        uint32_t abase = sbase + SQ_OFF + arow*128 + (sel >> 1)*16;
        #pragma unroll
        for (int g = 0; g < 4; ++g)
            LDSM_X4(aF[mt][g][0], aF[mt][g][1], aF[mt][g][2], aF[mt][g][3], abase + g*32);
    }

    // PV accumulators: d[mt][0..3]; cols 2t,2t+1 (t=lane&3):
    //   t=0 -> {A0,A1}, t=1 -> {A2,l}, t>=2 -> zeros
    float d[2][4];
    #pragma unroll
    for (int mt = 0; mt < 2; ++mt)
        #pragma unroll
        for (int i = 0; i < 4; ++i) d[mt][i] = 0.f;

    const int tq = lane & 3, gq = lane >> 2;

    #pragma unroll 1
    for (int ti = 0; ti < 8; ++ti) {
        if (ti < 7) {
            const size_t kb = base + (size_t)z*1024 + (size_t)(ti+1)*128;
            uint32_t db  = sbase + SK_OFF + ((ti+1) & 1)*KTILEB;
            uint32_t dvb = sbase + VWP_OFF + ((ti+1) & 1)*VWPB;
            #pragma unroll
            for (int k = 0; k < 4; ++k) {
                int i = tid + k*256;
                int rr = i >> 3, sg = i & 7;
                cp16(db + rr*RSTRK + sg*16,
                     (const unsigned char*)g_kp + (kb + rr)*128 + sg*16);
            }
            if (tid < 128)
                cp16(dvb + tid*16, g_vwp + (kb >> 1)*8 + tid*4);
            CP_COMMIT();
            CP_WAIT(1);
        } else {
            CP_WAIT(0);
        }
        __syncthreads();

        const uint32_t sk  = sbase + SK_OFF + (ti & 1)*KTILEB;
        const uint32_t svw = sbase + VWP_OFF + (ti & 1)*VWPB;

        #pragma unroll 2
        for (int jp = 0; jp < 8; ++jp) {
            // B fragments for QK (two n-tiles of the pair)
            uint32_t be[8], bo_[8];
            {
                uint32_t bb = sk + ((2*jp)*8 + lr)*RSTRK + sel*16;
                LDSM_X4(be[0], be[1], be[2], be[3], bb);
                LDSM_X4(be[4], be[5], be[6], be[7], bb + 64);
                uint32_t bb2 = sk + ((2*jp+1)*8 + lr)*RSTRK + sel*16;
                LDSM_X4(bo_[0], bo_[1], bo_[2], bo_[3], bb2);
                LDSM_X4(bo_[4], bo_[5], bo_[6], bo_[7], bb2 + 64);
            }
            // PV B fragments (pre-packed)
            uint32_t pb0, pb1;
            {
                uint32_t va0, va1;
                asm volatile("ld.shared.b32 %0, [%1];" : "=r"(va0)
                             : "r"(svw + ((jp*8 + tq)*8 + gq)*4));
                asm volatile("ld.shared.b32 %0, [%1];" : "=r"(va1)
                             : "r"(svw + ((jp*8 + 4 + tq)*8 + gq)*4));
                pb0 = va0; pb1 = va1;
            }

            #pragma unroll
            for (int mt = 0; mt < 2; ++mt) {
                float e0=0.f,e1=0.f,e2=0.f,e3=0.f;   // j even scores
                float o0=0.f,o1=0.f,o2=0.f,o3=0.f;   // j odd scores
                MMA16816(e0,e1,e2,e3, aF[mt][0][0],aF[mt][0][1],aF[mt][0][2],aF[mt][0][3], be[0],be[1]);
                MMA16816(o0,o1,o2,o3, aF[mt][0][0],aF[mt][0][1],aF[mt][0][2],aF[mt][0][3], bo_[0],bo_[1]);
                MMA16816(e0,e1,e2,e3, aF[mt][1][0],aF[mt][1][1],aF[mt][1][2],aF[mt][1][3], be[2],be[3]);
                MMA16816(o0,o1,o2,o3, aF[mt][1][0],aF[mt][1][1],aF[mt][1][2],aF[mt][1][3], bo_[2],bo_[3]);
                MMA16816(e0,e1,e2,e3, aF[mt][0][0],aF[mt][0][1],aF[mt][0][2],aF[mt][0][3], be[4],be[5]);
                MMA16816(o0,o1,o2,o3, aF[mt][0][0],aF[mt][0][1],aF[mt][0][2],aF[mt][0][3], bo_[4],bo_[5]);
                MMA16816(e0,e1,e2,e3, aF[mt][1][0],aF[mt][1][1],aF[mt][1][2],aF[mt][1][3], be[6],be[7]);
                MMA16816(o0,o1,o2,o3, aF[mt][1][0],aF[mt][1][1],aF[mt][1][2],aF[mt][1][3], bo_[6],bo_[7]);
                MMA16816(e0,e1,e2,e3, aF[mt][2][0],aF[mt][2][1],aF[mt][2][2],aF[mt][2][3], be[0],be[1]);
                MMA16816(o0,o1,o2,o3, aF[mt][2][0],aF[mt][2][1],aF[mt][2][2],aF[mt][2][3], bo_[0],bo_[1]);
                MMA16816(e0,e1,e2,e3, aF[mt][3][0],aF[mt][3][1],aF[mt][3][2],aF[mt][3][3], be[2],be[3]);
                MMA16816(o0,o1,o2,o3, aF[mt][3][0],aF[mt][3][1],aF[mt][3][2],aF[mt][3][3], bo_[2],bo_[3]);

                float p0 = ex2f(e0), p1 = ex2f(e1), p2 = ex2f(e2), p3 = ex2f(e3);
                float p4 = ex2f(o0), p5 = ex2f(o1), p6 = ex2f(o2), p7 = ex2f(o3);
                uint32_t a0 = pkbf(p0, p1);
                uint32_t a1 = pkbf(p2, p3);
                uint32_t a2 = pkbf(p4, p5);
                uint32_t a3 = pkbf(p6, p7);
                MMA16816(d[mt][0], d[mt][1], d[mt][2], d[mt][3],
                         a0, a1, a2, a3, pb0, pb1);
            }
        }
        __syncthreads();
    }

    // gather: t=0 lanes hold {A0,A1}; t=1 lanes hold {A2,l}; shuffle-combine
    #pragma unroll
    for (int mt = 0; mt < 2; ++mt) {
        float az_r0 = __shfl_xor_sync(0xffffffffu, d[mt][0], 1);  // from t^1
        float l_r0  = __shfl_xor_sync(0xffffffffu, d[mt][1], 1);
        float az_r1 = __shfl_xor_sync(0xffffffffu, d[mt][2], 1);
        float l_r1  = __shfl_xor_sync(0xffffffffu, d[mt][3], 1);
        if (tq == 0) {
            size_t r = base + q0 + wid*32 + mt*16 + gq;
            g_part[(size_t)z*NROWS + r]     = make_float4(l_r0, d[mt][0], d[mt][1], az_r0);
            g_part[(size_t)z*NROWS + r + 8] = make_float4(l_r1, d[mt][2], d[mt][3], az_r1);
        }
    }
}

// ---------------------------------------------------------------------------
// Finalize: combine 2 split-K partials, normalize, add constant.
// ---------------------------------------------------------------------------
__global__ __launch_bounds__(256) void finalize_kernel(
    float* __restrict__ out,
    const float* __restrict__ bv,
    const float* __restrict__ Wo,
    const float* __restrict__ bo) {
    __shared__ float sCST[3];
    const int tid = threadIdx.x;
    if (tid < 3) {
        float s = bo[tid];
        #pragma unroll
        for (int d = 0; d < DK; ++d) {
            float w = 0.f;
            #pragma unroll
            for (int h = 0; h < 16; ++h) w += Wo[(h*DK + d)*3 + tid];
            s = fmaf(bv[d], w, s);
        }
        sCST[tid] = s;
    }
    __syncthreads();
    size_t row = (size_t)blockIdx.x * 256 + tid;
    float4 p0 = g_part[row];
    float4 p1 = g_part[NROWS + row];
    float inv = 1.0f / (p0.x + p1.x);
    out[row*3 + 0] = fmaf(p0.y + p1.y, inv, sCST[0]);
    out[row*3 + 1] = fmaf(p0.z + p1.z, inv, sCST[1]);
    out[row*3 + 2] = fmaf(p0.w + p1.w, inv, sCST[2]);
}

extern "C" void kernel_launch(void* const* d_in, const int* in_sizes, int n_in,
                              void* d_out, int out_size) {
    const float* qin = (const float*)d_in[0];
    const float* kin = (const float*)d_in[1];
    const float* vin = (const float*)d_in[2];
    const float* Wq  = (const float*)d_in[3];
    const float* bq  = (const float*)d_in[4];
    const float* Wk  = (const float*)d_in[5];
    const float* bk  = (const float*)d_in[6];
    const float* Wv  = (const float*)d_in[7];
    const float* bv  = (const float*)d_in[8];
    const float* Wo  = (const float*)d_in[9];
    const float* bo  = (const float*)d_in[10];
    float* out = (float*)d_out;

    cudaFuncSetAttribute(flash8_kernel,
                         cudaFuncAttributeMaxDynamicSharedMemorySize, SMEM_BYTES);
    cudaFuncSetAttribute(proj4_kernel,
                         cudaFuncAttributeMaxDynamicSharedMemorySize, PJ_SMEM);
    proj4_kernel<<<dim3(NROWS/128, 3), 128, PJ_SMEM>>>(qin, kin, vin, Wq, bq, Wk, bk, Wv, Wo);
    flash8_kernel<<<dim3(SS/256, BB, 2), 256, SMEM_BYTES>>>();
    finalize_kernel<<<NROWS/256, 256>>>(out, bv, Wo, bo);
}

// round 10
// speedup vs baseline: 1.2744x; 1.0317x over previous
#include <cuda_runtime.h>
#include <cuda_bf16.h>
#include <math.h>
#include <cstdint>

#define BB 32
#define SS 2048
#define FF 128
#define DK 32
#define NROWS (BB*SS)

// Packed projections, 64 bf16 per row (128B): [hi(32) | lo(32)]
// q pre-scaled by log2(e)/sqrt(32)  (scores in log2 domain -> ex2)
__device__ __nv_bfloat16 g_qp[NROWS*64];
__device__ __nv_bfloat16 g_kp[NROWS*64];
// PV B-operand, pre-packed bf16x2: per key-pair p, 8 cols g:
//   g<3: {lo=vw[2p][g], hi=vw[2p+1][g]}, g==3: {1,1}, g>3: 0
__device__ uint32_t g_vwp[(NROWS/2)*8];
__device__ float4 g_part[2*NROWS];         // split-K partials {l, A0, A1, A2}

static __device__ __forceinline__ uint32_t smem_u32(const void* p) {
    uint32_t a;
    asm("{ .reg .u64 t; cvta.to.shared.u64 t, %1; cvt.u32.u64 %0, t; }" : "=r"(a) : "l"(p));
    return a;
}
static __device__ __forceinline__ void cp16(uint32_t dst, const void* src) {
    asm volatile("cp.async.cg.shared.global [%0], [%1], 16;" :: "r"(dst), "l"(src) : "memory");
}
#define CP_COMMIT() asm volatile("cp.async.commit_group;" ::: "memory")
#define CP_WAIT(n)  asm volatile("cp.async.wait_group %0;" :: "n"(n) : "memory")

static __device__ __forceinline__ float ex2f(float x) {
    float y; asm("ex2.approx.f32 %0, %1;" : "=f"(y) : "f"(x)); return y;
}
// pack {lo, hi} floats -> bf16x2 (memory order: lo first)
static __device__ __forceinline__ uint32_t pkbf(float lo, float hi) {
    uint32_t r;
    asm("cvt.rn.bf16x2.f32 %0, %1, %2;" : "=r"(r) : "f"(hi), "f"(lo));
    return r;
}

#define LDSM_X4(r0,r1,r2,r3,addr) \
    asm volatile("ldmatrix.sync.aligned.m8n8.x4.shared.b16 {%0,%1,%2,%3}, [%4];" \
        : "=r"(r0), "=r"(r1), "=r"(r2), "=r"(r3) : "r"(addr))

#define MMA16816(c0,c1,c2,c3,a0,a1,a2,a3,b0,b1) \
    asm volatile("mma.sync.aligned.m16n8k16.row.col.f32.bf16.bf16.f32 " \
        "{%0,%1,%2,%3}, {%4,%5,%6,%7}, {%8,%9}, {%0,%1,%2,%3};" \
        : "+f"(c0), "+f"(c1), "+f"(c2), "+f"(c3) \
        : "r"(a0), "r"(a1), "r"(a2), "r"(a3), "r"(b0), "r"(b1))

// ---------------------------------------------------------------------------
// Projection via HMMA: grid (128, 3), 256 threads, 64 rows/block.
// phases 0/1 (Q/K): 3-term bf16-split GEMM [64x128]@[128x32] on tensor cores.
// phase 2 (V): scalar path (3 cols), emits packed g_vwp fragments.
// ---------------------------------------------------------------------------
#define PJ_SWBH 0
#define PJ_SWBL 8704
#define PJ_SXAH 17408
#define PJ_SXAL 34816
#define PJ_SBIAS 52224
#define PJ_SMEM 52480
// V-phase layout (same buffer): sWv@0, sWoE@1536, sVS@2048, vbuf@3072

__global__ __launch_bounds__(256) void proj5_kernel(
    const float* __restrict__ qin, const float* __restrict__ kin, const float* __restrict__ vin,
    const float* __restrict__ Wq, const float* __restrict__ bq,
    const float* __restrict__ Wk, const float* __restrict__ bk,
    const float* __restrict__ Wv, const float* __restrict__ Wo) {
    extern __shared__ __align__(16) unsigned char dsm[];
    const int tid  = threadIdx.x;
    const int wid  = tid >> 5, lane = tid & 31;
    const int phase = blockIdx.y;
    const size_t row0 = (size_t)blockIdx.x * 64;
    const uint32_t sb = smem_u32(dsm);

    if (phase < 2) {
        const float* W  = phase ? Wk : Wq;
        const float* bb = phase ? bk : bq;
        const float* in = phase ? kin : qin;
        __nv_bfloat16* gout = phase ? g_kp : g_qp;
        const float qs = phase ? 1.0f
                               : 0.17677669529663687f * 1.4426950408889634f;

        // ---- W load + split + transposed store: swb[col][f], stride 272B ----
        {
            int c = tid & 31, fg = tid >> 5;
            __nv_bfloat16* wh = (__nv_bfloat16*)(dsm + PJ_SWBH);
            __nv_bfloat16* wl = (__nv_bfloat16*)(dsm + PJ_SWBL);
            #pragma unroll
            for (int i = 0; i < 16; ++i) {
                int f = fg*16 + i;
                float w = W[f*32 + c];
                __nv_bfloat16 h = __float2bfloat16(w);
                wh[c*136 + f] = h;
                wl[c*136 + f] = __float2bfloat16(w - __bfloat162float(h));
            }
        }
        if (tid < 32) ((float*)(dsm + PJ_SBIAS))[tid] = bb[tid];

        // ---- X load + split: sxa[row][f], stride 272B ----
        {
            int xr = tid >> 2;
            const float4* src = (const float4*)in + (row0 + xr)*32;
            #pragma unroll
            for (int j = 0; j < 8; ++j) {
                int s = (tid & 3) + j*4;           // float4 index in row
                float4 x = src[s];
                uint32_t h0 = pkbf(x.x, x.y);
                uint32_t h1 = pkbf(x.z, x.w);
                float f00 = __uint_as_float(h0 << 16);
                float f01 = __uint_as_float(h0 & 0xFFFF0000u);
                float f10 = __uint_as_float(h1 << 16);
                float f11 = __uint_as_float(h1 & 0xFFFF0000u);
                uint32_t l0 = pkbf(x.x - f00, x.y - f01);
                uint32_t l1 = pkbf(x.z - f10, x.w - f11);
                *(uint2*)(dsm + PJ_SXAH + xr*272 + s*8) = make_uint2(h0, h1);
                *(uint2*)(dsm + PJ_SXAL + xr*272 + s*8) = make_uint2(l0, l1);
            }
        }
        __syncthreads();

        // ---- MMA: warp (mt = wid&3) x (nh = wid>>2) -> 16 rows x 16 cols ----
        const int mt = wid & 3, nh = wid >> 2;
        const int lr = lane & 7, sel = lane >> 3;
        const uint32_t axh = sb + PJ_SXAH + (mt*16 + lr + (sel & 1)*8)*272 + (sel >> 1)*16;
        const uint32_t axl = sb + PJ_SXAL + (mt*16 + lr + (sel & 1)*8)*272 + (sel >> 1)*16;
        uint32_t bwh[2], bwl[2];
        #pragma unroll
        for (int nt = 0; nt < 2; ++nt) {
            bwh[nt] = sb + PJ_SWBH + ((nh*2 + nt)*8 + lr)*272 + sel*16;
            bwl[nt] = sb + PJ_SWBL + ((nh*2 + nt)*8 + lr)*272 + sel*16;
        }

        float c0[4] = {0.f,0.f,0.f,0.f}, c1[4] = {0.f,0.f,0.f,0.f};
        #pragma unroll
        for (int g2 = 0; g2 < 4; ++g2) {
            uint32_t ah[8], al[8];
            LDSM_X4(ah[0], ah[1], ah[2], ah[3], axh + (2*g2)*32);
            LDSM_X4(ah[4], ah[5], ah[6], ah[7], axh + (2*g2+1)*32);
            LDSM_X4(al[0], al[1], al[2], al[3], axl + (2*g2)*32);
            LDSM_X4(al[4], al[5], al[6], al[7], axl + (2*g2+1)*32);
            #pragma unroll
            for (int nt = 0; nt < 2; ++nt) {
                float* cc = nt ? c1 : c0;
                uint32_t bh[4], bl[4];
                LDSM_X4(bh[0], bh[1], bh[2], bh[3], bwh[nt] + g2*64);
                LDSM_X4(bl[0], bl[1], bl[2], bl[3], bwl[nt] + g2*64);
                MMA16816(cc[0],cc[1],cc[2],cc[3], ah[0],ah[1],ah[2],ah[3], bh[0],bh[1]); // xh.wh even
                MMA16816(cc[0],cc[1],cc[2],cc[3], ah[4],ah[5],ah[6],ah[7], bh[2],bh[3]); // xh.wh odd
                MMA16816(cc[0],cc[1],cc[2],cc[3], ah[0],ah[1],ah[2],ah[3], bl[0],bl[1]); // xh.wl
                MMA16816(cc[0],cc[1],cc[2],cc[3], ah[4],ah[5],ah[6],ah[7], bl[2],bl[3]);
                MMA16816(cc[0],cc[1],cc[2],cc[3], al[0],al[1],al[2],al[3], bh[0],bh[1]); // xl.wh
                MMA16816(cc[0],cc[1],cc[2],cc[3], al[4],al[5],al[6],al[7], bh[2],bh[3]);
            }
        }

        // ---- epilogue: bias+scale, split hi/lo, write packed u32 ----
        {
            const float* sBias = (const float*)(dsm + PJ_SBIAS);
            const int gq = lane >> 2, tq = lane & 3;
            #pragma unroll
            for (int nt = 0; nt < 2; ++nt) {
                const float* cc = nt ? c1 : c0;
                int colp = nh*16 + nt*8 + tq*2;
                float b0 = sBias[colp], b1 = sBias[colp+1];
                #pragma unroll
                for (int hf = 0; hf < 2; ++hf) {
                    size_t rrow = row0 + mt*16 + gq + hf*8;
                    float v0 = (cc[hf*2+0] + b0) * qs;
                    float v1 = (cc[hf*2+1] + b1) * qs;
                    uint32_t hp = pkbf(v0, v1);
                    float h0 = __uint_as_float(hp << 16);
                    float h1 = __uint_as_float(hp & 0xFFFF0000u);
                    uint32_t lp = pkbf(v0 - h0, v1 - h1);
                    *(uint32_t*)((unsigned char*)gout + rrow*128 + colp*2)      = hp;
                    *(uint32_t*)((unsigned char*)gout + rrow*128 + 64 + colp*2) = lp;
                }
            }
        }
    } else {
        // ---- V: vw = v_in @ (Wv @ Wo_eff); emit packed bf16x2 fragments ----
        float* sWv  = (float*)dsm;                 // [FF*3]
        float* sWoE = (float*)(dsm + 1536);        // [DK*3]
        float* sVS  = (float*)(dsm + 2048);        // [64][4]
        float* vbuf = (float*)(dsm + 3072);        // [64][128]

        if (tid < 96) {
            int d = tid / 3, f = tid - d*3;
            float s = 0.f;
            #pragma unroll
            for (int h = 0; h < 16; ++h) s += Wo[(h*DK + d)*3 + f];
            sWoE[tid] = s;
        }
        {
            int xr = tid >> 2;
            const float4* src = (const float4*)vin + (row0 + xr)*32;
            #pragma unroll
            for (int j = 0; j < 8; ++j) {
                int s = (tid & 3) + j*4;
                ((float4*)vbuf)[xr*32 + s] = src[s];
            }
        }
        __syncthreads();
        for (int i = tid; i < FF*3; i += 256) {
            int r = i / 3, f = i - r*3;
            float s = 0.f;
            #pragma unroll
            for (int d = 0; d < DK; ++d) s = fmaf(Wv[r*DK + d], sWoE[d*3 + f], s);
            sWv[i] = s;
        }
        __syncthreads();
        if (tid < 192) {
            int r = tid / 3, f = tid - r*3;
            const float* buf = vbuf + r*FF;
            float s0=0.f,s1=0.f,s2=0.f,s3=0.f;
            #pragma unroll 8
            for (int ff = 0; ff < FF; ff += 4) {
                s0 = fmaf(buf[ff+0], sWv[(ff+0)*3+f], s0);
                s1 = fmaf(buf[ff+1], sWv[(ff+1)*3+f], s1);
                s2 = fmaf(buf[ff+2], sWv[(ff+2)*3+f], s2);
                s3 = fmaf(buf[ff+3], sWv[(ff+3)*3+f], s3);
            }
            sVS[r*4 + f] = (s0+s1)+(s2+s3);
        }
        __syncthreads();
        {   // pack: 32 pairs x 8 cols = 256 words
            int p = tid >> 3, g = tid & 7;
            uint32_t w;
            if (g < 3)       w = pkbf(sVS[(2*p)*4 + g], sVS[(2*p+1)*4 + g]);
            else if (g == 3) w = 0x3F803F80u;       // {1.0bf, 1.0bf}
            else             w = 0u;
            g_vwp[(row0 >> 1)*8 + p*8 + g] = w;
        }
    }
}

// ---------------------------------------------------------------------------
// Flash kernel: 256 threads (8 warps x 32 q-rows), q-tile 256, split-K 2-way.
// QK^T via bf16-split HMMA; softmax (no max) via ex2; PV via HMMA with
// pre-packed vwp B-fragments (col 3 = ones -> l accumulated by the MMA).
// ---------------------------------------------------------------------------
#define RSTRK 144
#define SQ_OFF 0
#define SK_OFF 32768                       // Q: 256*128
#define KTILEB (128*RSTRK)                 // 18432
#define VWP_OFF (SK_OFF + 2*KTILEB)        // 69632
#define VWPB 2048
#define SMEM_BYTES (VWP_OFF + 2*VWPB)      // 73728

__global__ __launch_bounds__(256, 3)
void flash8_kernel(void) {
    extern __shared__ __align__(16) unsigned char smem[];
    const int tid  = threadIdx.x;
    const int wid  = tid >> 5, lane = tid & 31;
    const size_t base = (size_t)blockIdx.y * SS;
    const int q0 = blockIdx.x * 256;
    const int z  = blockIdx.z;
    const uint32_t sbase = smem_u32(smem);

    // prologue: Q tile (group 0), first K tile + vwp (group 1)
    #pragma unroll
    for (int k = 0; k < 8; ++k) {
        int i = tid + k*256;
        cp16(sbase + SQ_OFF + i*16,
             (const unsigned char*)g_qp + (base + q0)*128 + i*16);
    }
    CP_COMMIT();
    {
        const size_t kb = base + (size_t)z * 1024;
        #pragma unroll
        for (int k = 0; k < 4; ++k) {
            int i = tid + k*256;
            int rr = i >> 3, sg = i & 7;
            cp16(sbase + SK_OFF + rr*RSTRK + sg*16,
                 (const unsigned char*)g_kp + (kb + rr)*128 + sg*16);
        }
        if (tid < 128)
            cp16(sbase + VWP_OFF + tid*16, g_vwp + (kb >> 1)*8 + tid*4);
    }
    CP_COMMIT();
    CP_WAIT(1);            // Q ready
    __syncthreads();

    const int lr  = lane & 7;
    const int sel = lane >> 3;

    // A fragments (loop-invariant): qh steps {0,1} then ql steps {0,1}
    uint32_t aF[2][4][4];
    #pragma unroll
    for (int mt = 0; mt < 2; ++mt) {
        int arow = wid*32 + mt*16 + lr + (sel & 1)*8;
        uint32_t abase = sbase + SQ_OFF + arow*128 + (sel >> 1)*16;
        #pragma unroll
        for (int g = 0; g < 4; ++g)
            LDSM_X4(aF[mt][g][0], aF[mt][g][1], aF[mt][g][2], aF[mt][g][3], abase + g*32);
    }

    // PV accumulators: d[mt][0..3]; cols 2t,2t+1 (t=lane&3):
    //   t=0 -> {A0,A1}, t=1 -> {A2,l}, t>=2 -> zeros
    float d[2][4];
    #pragma unroll
    for (int mt = 0; mt < 2; ++mt)
        #pragma unroll
        for (int i = 0; i < 4; ++i) d[mt][i] = 0.f;

    const int tq = lane & 3, gq = lane >> 2;

    #pragma unroll 1
    for (int ti = 0; ti < 8; ++ti) {
        if (ti < 7) {
            const size_t kb = base + (size_t)z*1024 + (size_t)(ti+1)*128;
            uint32_t db  = sbase + SK_OFF + ((ti+1) & 1)*KTILEB;
            uint32_t dvb = sbase + VWP_OFF + ((ti+1) & 1)*VWPB;
            #pragma unroll
            for (int k = 0; k < 4; ++k) {
                int i = tid + k*256;
                int rr = i >> 3, sg = i & 7;
                cp16(db + rr*RSTRK + sg*16,
                     (const unsigned char*)g_kp + (kb + rr)*128 + sg*16);
            }
            if (tid < 128)
                cp16(dvb + tid*16, g_vwp + (kb >> 1)*8 + tid*4);
            CP_COMMIT();
            CP_WAIT(1);
        } else {
            CP_WAIT(0);
        }
        __syncthreads();

        const uint32_t sk  = sbase + SK_OFF + (ti & 1)*KTILEB;
        const uint32_t svw = sbase + VWP_OFF + (ti & 1)*VWPB;

        #pragma unroll 2
        for (int jp = 0; jp < 8; ++jp) {
            // B fragments for QK (two n-tiles of the pair)
            uint32_t be[8], bo_[8];
            {
                uint32_t bb = sk + ((2*jp)*8 + lr)*RSTRK + sel*16;
                LDSM_X4(be[0], be[1], be[2], be[3], bb);
                LDSM_X4(be[4], be[5], be[6], be[7], bb + 64);
                uint32_t bb2 = sk + ((2*jp+1)*8 + lr)*RSTRK + sel*16;
                LDSM_X4(bo_[0], bo_[1], bo_[2], bo_[3], bb2);
                LDSM_X4(bo_[4], bo_[5], bo_[6], bo_[7], bb2 + 64);
            }
            // PV B fragments (pre-packed)
            uint32_t pb0, pb1;
            {
                uint32_t va0, va1;
                asm volatile("ld.shared.b32 %0, [%1];" : "=r"(va0)
                             : "r"(svw + ((jp*8 + tq)*8 + gq)*4));
                asm volatile("ld.shared.b32 %0, [%1];" : "=r"(va1)
                             : "r"(svw + ((jp*8 + 4 + tq)*8 + gq)*4));
                pb0 = va0; pb1 = va1;
            }

            #pragma unroll
            for (int mt = 0; mt < 2; ++mt) {
                float e0=0.f,e1=0.f,e2=0.f,e3=0.f;   // j even scores
                float o0=0.f,o1=0.f,o2=0.f,o3=0.f;   // j odd scores
                MMA16816(e0,e1,e2,e3, aF[mt][0][0],aF[mt][0][1],aF[mt][0][2],aF[mt][0][3], be[0],be[1]);
                MMA16816(o0,o1,o2,o3, aF[mt][0][0],aF[mt][0][1],aF[mt][0][2],aF[mt][0][3], bo_[0],bo_[1]);
                MMA16816(e0,e1,e2,e3, aF[mt][1][0],aF[mt][1][1],aF[mt][1][2],aF[mt][1][3], be[2],be[3]);
                MMA16816(o0,o1,o2,o3, aF[mt][1][0],aF[mt][1][1],aF[mt][1][2],aF[mt][1][3], bo_[2],bo_[3]);
                MMA16816(e0,e1,e2,e3, aF[mt][0][0],aF[mt][0][1],aF[mt][0][2],aF[mt][0][3], be[4],be[5]);
                MMA16816(o0,o1,o2,o3, aF[mt][0][0],aF[mt][0][1],aF[mt][0][2],aF[mt][0][3], bo_[4],bo_[5]);
                MMA16816(e0,e1,e2,e3, aF[mt][1][0],aF[mt][1][1],aF[mt][1][2],aF[mt][1][3], be[6],be[7]);
                MMA16816(o0,o1,o2,o3, aF[mt][1][0],aF[mt][1][1],aF[mt][1][2],aF[mt][1][3], bo_[6],bo_[7]);
                MMA16816(e0,e1,e2,e3, aF[mt][2][0],aF[mt][2][1],aF[mt][2][2],aF[mt][2][3], be[0],be[1]);
                MMA16816(o0,o1,o2,o3, aF[mt][2][0],aF[mt][2][1],aF[mt][2][2],aF[mt][2][3], bo_[0],bo_[1]);
                MMA16816(e0,e1,e2,e3, aF[mt][3][0],aF[mt][3][1],aF[mt][3][2],aF[mt][3][3], be[2],be[3]);
                MMA16816(o0,o1,o2,o3, aF[mt][3][0],aF[mt][3][1],aF[mt][3][2],aF[mt][3][3], bo_[2],bo_[3]);

                float p0 = ex2f(e0), p1 = ex2f(e1), p2 = ex2f(e2), p3 = ex2f(e3);
                float p4 = ex2f(o0), p5 = ex2f(o1), p6 = ex2f(o2), p7 = ex2f(o3);
                uint32_t a0 = pkbf(p0, p1);
                uint32_t a1 = pkbf(p2, p3);
                uint32_t a2 = pkbf(p4, p5);
                uint32_t a3 = pkbf(p6, p7);
                MMA16816(d[mt][0], d[mt][1], d[mt][2], d[mt][3],
                         a0, a1, a2, a3, pb0, pb1);
            }
        }
        __syncthreads();
    }

    // gather: t=0 lanes hold {A0,A1}; t=1 lanes hold {A2,l}; shuffle-combine
    #pragma unroll
    for (int mt = 0; mt < 2; ++mt) {
        float az_r0 = __shfl_xor_sync(0xffffffffu, d[mt][0], 1);  // from t^1
        float l_r0  = __shfl_xor_sync(0xffffffffu, d[mt][1], 1);
        float az_r1 = __shfl_xor_sync(0xffffffffu, d[mt][2], 1);
        float l_r1  = __shfl_xor_sync(0xffffffffu, d[mt][3], 1);
        if (tq == 0) {
            size_t r = base + q0 + wid*32 + mt*16 + gq;
            g_part[(size_t)z*NROWS + r]     = make_float4(l_r0, d[mt][0], d[mt][1], az_r0);
            g_part[(size_t)z*NROWS + r + 8] = make_float4(l_r1, d[mt][2], d[mt][3], az_r1);
        }
    }
}

// ---------------------------------------------------------------------------
// Finalize: combine 2 split-K partials, normalize, add constant.
// ---------------------------------------------------------------------------
__global__ __launch_bounds__(256) void finalize_kernel(
    float* __restrict__ out,
    const float* __restrict__ bv,
    const float* __restrict__ Wo,
    const float* __restrict__ bo) {
    __shared__ float sCST[3];
    const int tid = threadIdx.x;
    if (tid < 3) {
        float s = bo[tid];
        #pragma unroll
        for (int d = 0; d < DK; ++d) {
            float w = 0.f;
            #pragma unroll
            for (int h = 0; h < 16; ++h) w += Wo[(h*DK + d)*3 + tid];
            s = fmaf(bv[d], w, s);
        }
        sCST[tid] = s;
    }
    __syncthreads();
    size_t row = (size_t)blockIdx.x * 256 + tid;
    float4 p0 = g_part[row];
    float4 p1 = g_part[NROWS + row];
    float inv = 1.0f / (p0.x + p1.x);
    out[row*3 + 0] = fmaf(p0.y + p1.y, inv, sCST[0]);
    out[row*3 + 1] = fmaf(p0.z + p1.z, inv, sCST[1]);
    out[row*3 + 2] = fmaf(p0.w + p1.w, inv, sCST[2]);
}

extern "C" void kernel_launch(void* const* d_in, const int* in_sizes, int n_in,
                              void* d_out, int out_size) {
    const float* qin = (const float*)d_in[0];
    const float* kin = (const float*)d_in[1];
    const float* vin = (const float*)d_in[2];
    const float* Wq  = (const float*)d_in[3];
    const float* bq  = (const float*)d_in[4];
    const float* Wk  = (const float*)d_in[5];
    const float* bk  = (const float*)d_in[6];
    const float* Wv  = (const float*)d_in[7];
    const float* bv  = (const float*)d_in[8];
    const float* Wo  = (const float*)d_in[9];
    const float* bo  = (const float*)d_in[10];
    float* out = (float*)d_out;

    cudaFuncSetAttribute(flash8_kernel,
                         cudaFuncAttributeMaxDynamicSharedMemorySize, SMEM_BYTES);
    cudaFuncSetAttribute(proj5_kernel,
                         cudaFuncAttributeMaxDynamicSharedMemorySize, PJ_SMEM);
    proj5_kernel<<<dim3(NROWS/64, 3), 256, PJ_SMEM>>>(qin, kin, vin, Wq, bq, Wk, bk, Wv, Wo);
    flash8_kernel<<<dim3(SS/256, BB, 2), 256, SMEM_BYTES>>>();
    finalize_kernel<<<NROWS/256, 256>>>(out, bv, Wo, bo);
}

// round 11
// speedup vs baseline: 1.3196x; 1.0355x over previous
#include <cuda_runtime.h>
#include <cuda_bf16.h>
#include <math.h>
#include <cstdint>

#define BB 32
#define SS 2048
#define FF 128
#define DK 32
#define NROWS (BB*SS)

// Packed projections, 64 bf16 per row (128B): [hi(32) | lo(32)]
// q pre-scaled by log2(e)/sqrt(32)  (scores in log2 domain -> ex2)
__device__ __nv_bfloat16 g_qp[NROWS*64];
__device__ __nv_bfloat16 g_kp[NROWS*64];
// PV B-operand, pre-packed bf16x2: per key-pair p, 8 cols g:
//   g<3: {lo=vw[2p][g], hi=vw[2p+1][g]}, g==3: {1,1}, g>3: 0
__device__ uint32_t g_vwp[(NROWS/2)*8];
__device__ float4 g_part[2*NROWS];         // split-K partials {l, A0, A1, A2}
// Pre-split W images (ldmatrix-ready): per phase 8704 bf16 = 4352 hi + 4352 lo,
// layout img[c*136 + f] (c = out col 0..31, f = 0..127, 8 pad per row)
__device__ __nv_bfloat16 g_wimg[2][8704];
__device__ float g_wveff[FF*3];            // Wv @ Wo_eff

static __device__ __forceinline__ uint32_t smem_u32(const void* p) {
    uint32_t a;
    asm("{ .reg .u64 t; cvta.to.shared.u64 t, %1; cvt.u32.u64 %0, t; }" : "=r"(a) : "l"(p));
    return a;
}
static __device__ __forceinline__ void cp16(uint32_t dst, const void* src) {
    asm volatile("cp.async.cg.shared.global [%0], [%1], 16;" :: "r"(dst), "l"(src) : "memory");
}
#define CP_COMMIT() asm volatile("cp.async.commit_group;" ::: "memory")
#define CP_WAIT(n)  asm volatile("cp.async.wait_group %0;" :: "n"(n) : "memory")

static __device__ __forceinline__ float ex2f(float x) {
    float y; asm("ex2.approx.f32 %0, %1;" : "=f"(y) : "f"(x)); return y;
}
// pack {lo, hi} floats -> bf16x2 (memory order: lo first)
static __device__ __forceinline__ uint32_t pkbf(float lo, float hi) {
    uint32_t r;
    asm("cvt.rn.bf16x2.f32 %0, %1, %2;" : "=r"(r) : "f"(hi), "f"(lo));
    return r;
}
// split a float2 into bf16x2 hi + bf16x2 lo words
static __device__ __forceinline__ void split2(float2 x, uint32_t& h, uint32_t& l) {
    h = pkbf(x.x, x.y);
    float f0 = __uint_as_float(h << 16);
    float f1 = __uint_as_float(h & 0xFFFF0000u);
    l = pkbf(x.x - f0, x.y - f1);
}

#define LDSM_X4(r0,r1,r2,r3,addr) \
    asm volatile("ldmatrix.sync.aligned.m8n8.x4.shared.b16 {%0,%1,%2,%3}, [%4];" \
        : "=r"(r0), "=r"(r1), "=r"(r2), "=r"(r3) : "r"(addr))

#define MMA16816(c0,c1,c2,c3,a0,a1,a2,a3,b0,b1) \
    asm volatile("mma.sync.aligned.m16n8k16.row.col.f32.bf16.bf16.f32 " \
        "{%0,%1,%2,%3}, {%4,%5,%6,%7}, {%8,%9}, {%0,%1,%2,%3};" \
        : "+f"(c0), "+f"(c1), "+f"(c2), "+f"(c3) \
        : "r"(a0), "r"(a1), "r"(a2), "r"(a3), "r"(b0), "r"(b1))

// ---------------------------------------------------------------------------
// Prep: build split/transposed W images + Wv_eff (runs once, 1 block).
// ---------------------------------------------------------------------------
__global__ __launch_bounds__(256) void prep_kernel(
    const float* __restrict__ Wq, const float* __restrict__ Wk,
    const float* __restrict__ Wv, const float* __restrict__ Wo) {
    __shared__ float sWoE[DK*3];
    const int tid = threadIdx.x;
    #pragma unroll
    for (int p = 0; p < 2; ++p) {
        const float* W = p ? Wk : Wq;
        __nv_bfloat16* img = g_wimg[p];
        int c = tid & 31, fg = tid >> 5;
        #pragma unroll
        for (int i = 0; i < 16; ++i) {
            int f = fg*16 + i;
            float w = W[f*32 + c];
            __nv_bfloat16 h = __float2bfloat16(w);
            img[c*136 + f]        = h;
            img[4352 + c*136 + f] = __float2bfloat16(w - __bfloat162float(h));
        }
    }
    if (tid < 96) {
        int d = tid / 3, f = tid - d*3;
        float s = 0.f;
        #pragma unroll
        for (int h = 0; h < 16; ++h) s += Wo[(h*DK + d)*3 + f];
        sWoE[tid] = s;
    }
    __syncthreads();
    for (int i = tid; i < FF*3; i += 256) {
        int r = i / 3, f = i - r*3;
        float s = 0.f;
        #pragma unroll
        for (int d = 0; d < DK; ++d) s = fmaf(Wv[r*DK + d], sWoE[d*3 + f], s);
        g_wveff[i] = s;
    }
}

// ---------------------------------------------------------------------------
// Projection: grid (512, 3), 256 threads, 128 rows/block.
// Q/K: A-fragments built in registers from global (no smem X); B from the
// pre-split W image (cp.async'd). 3-term bf16-split GEMM on HMMA.
// V: 4 threads/row + quad reduce, emits packed g_vwp fragments.
// ---------------------------------------------------------------------------
#define P6_SMEM 17536

__global__ __launch_bounds__(256) void proj6_kernel(
    const float* __restrict__ qin, const float* __restrict__ kin, const float* __restrict__ vin,
    const float* __restrict__ bq, const float* __restrict__ bk) {
    extern __shared__ __align__(16) unsigned char dsm[];
    const int tid  = threadIdx.x;
    const int wid  = tid >> 5, lane = tid & 31;
    const int phase = blockIdx.y;
    const size_t row0 = (size_t)blockIdx.x * 128;
    const uint32_t sb = smem_u32(dsm);

    if (phase < 2) {
        const float* in = phase ? kin : qin;
        const float* bb = phase ? bk : bq;
        __nv_bfloat16* gout = phase ? g_kp : g_qp;
        const float qs = phase ? 1.0f
                               : 0.17677669529663687f * 1.4426950408889634f;

        // stage pre-split W image (17408 B)
        for (int i = tid; i < 1088; i += 256)
            cp16(sb + i*16, (const unsigned char*)g_wimg[phase] + i*16);
        CP_COMMIT();

        // A fragments direct from global: warp = 16 rows x 32 cols
        const int gq = lane >> 2, tq = lane & 3;
        const float* rp0 = in + (row0 + wid*16 + gq)*128;
        const float* rp1 = rp0 + 8*128;
        uint32_t ah[8][4], al[8][4];
        #pragma unroll
        for (int g = 0; g < 8; ++g) {
            int cb = g*16 + tq*2;
            float2 x00 = *(const float2*)(rp0 + cb);
            float2 x10 = *(const float2*)(rp1 + cb);
            float2 x01 = *(const float2*)(rp0 + cb + 8);
            float2 x11 = *(const float2*)(rp1 + cb + 8);
            split2(x00, ah[g][0], al[g][0]);
            split2(x10, ah[g][1], al[g][1]);
            split2(x01, ah[g][2], al[g][2]);
            split2(x11, ah[g][3], al[g][3]);
        }
        CP_WAIT(0);
        __syncthreads();

        const int lr = lane & 7, sel = lane >> 3;
        float acc[4][4];
        #pragma unroll
        for (int nt = 0; nt < 4; ++nt)
            #pragma unroll
            for (int i = 0; i < 4; ++i) acc[nt][i] = 0.f;

        #pragma unroll
        for (int nt = 0; nt < 4; ++nt) {
            uint32_t bwh = sb + (nt*8 + lr)*272 + sel*16;
            uint32_t bwl = bwh + 8704;
            #pragma unroll
            for (int g2 = 0; g2 < 4; ++g2) {
                uint32_t bh[4], bl[4];
                LDSM_X4(bh[0], bh[1], bh[2], bh[3], bwh + g2*64);
                LDSM_X4(bl[0], bl[1], bl[2], bl[3], bwl + g2*64);
                int g0 = 2*g2, g1 = g0 + 1;
                MMA16816(acc[nt][0],acc[nt][1],acc[nt][2],acc[nt][3],
                         ah[g0][0],ah[g0][1],ah[g0][2],ah[g0][3], bh[0],bh[1]); // xh.wh
                MMA16816(acc[nt][0],acc[nt][1],acc[nt][2],acc[nt][3],
                         ah[g1][0],ah[g1][1],ah[g1][2],ah[g1][3], bh[2],bh[3]);
                MMA16816(acc[nt][0],acc[nt][1],acc[nt][2],acc[nt][3],
                         ah[g0][0],ah[g0][1],ah[g0][2],ah[g0][3], bl[0],bl[1]); // xh.wl
                MMA16816(acc[nt][0],acc[nt][1],acc[nt][2],acc[nt][3],
                         ah[g1][0],ah[g1][1],ah[g1][2],ah[g1][3], bl[2],bl[3]);
                MMA16816(acc[nt][0],acc[nt][1],acc[nt][2],acc[nt][3],
                         al[g0][0],al[g0][1],al[g0][2],al[g0][3], bh[0],bh[1]); // xl.wh
                MMA16816(acc[nt][0],acc[nt][1],acc[nt][2],acc[nt][3],
                         al[g1][0],al[g1][1],al[g1][2],al[g1][3], bh[2],bh[3]);
            }
        }

        // epilogue: bias + scale, split hi/lo, packed u32 stores
        #pragma unroll
        for (int nt = 0; nt < 4; ++nt) {
            int colp = nt*8 + tq*2;
            float b0 = bb[colp], b1 = bb[colp+1];
            #pragma unroll
            for (int hf = 0; hf < 2; ++hf) {
                size_t rrow = row0 + wid*16 + gq + hf*8;
                float v0 = (acc[nt][hf*2+0] + b0) * qs;
                float v1 = (acc[nt][hf*2+1] + b1) * qs;
                uint32_t hp = pkbf(v0, v1);
                float h0 = __uint_as_float(hp << 16);
                float h1 = __uint_as_float(hp & 0xFFFF0000u);
                uint32_t lp = pkbf(v0 - h0, v1 - h1);
                *(uint32_t*)((unsigned char*)gout + rrow*128 + colp*2)      = hp;
                *(uint32_t*)((unsigned char*)gout + rrow*128 + 64 + colp*2) = lp;
            }
        }
    } else {
        // V: vw rows via 4 threads/row + quad reduce, then pack fragments
        float* sWv = (float*)dsm;                 // [384]
        float* sVS = (float*)(dsm + 1536);        // [128][4]
        for (int i = tid; i < 384; i += 256) sWv[i] = g_wveff[i];
        __syncthreads();
        #pragma unroll
        for (int it = 0; it < 2; ++it) {
            int r = it*64 + (tid >> 2);
            const float* rp = vin + (row0 + r)*128 + (tid & 3)*32;
            float a0 = 0.f, a1 = 0.f, a2 = 0.f;
            #pragma unroll
            for (int f4 = 0; f4 < 8; ++f4) {
                float4 x = ((const float4*)rp)[f4];
                int f = (tid & 3)*32 + f4*4;
                a0 = fmaf(x.x, sWv[(f+0)*3+0], a0); a1 = fmaf(x.x, sWv[(f+0)*3+1], a1); a2 = fmaf(x.x, sWv[(f+0)*3+2], a2);
                a0 = fmaf(x.y, sWv[(f+1)*3+0], a0); a1 = fmaf(x.y, sWv[(f+1)*3+1], a1); a2 = fmaf(x.y, sWv[(f+1)*3+2], a2);
                a0 = fmaf(x.z, sWv[(f+2)*3+0], a0); a1 = fmaf(x.z, sWv[(f+2)*3+1], a1); a2 = fmaf(x.z, sWv[(f+2)*3+2], a2);
                a0 = fmaf(x.w, sWv[(f+3)*3+0], a0); a1 = fmaf(x.w, sWv[(f+3)*3+1], a1); a2 = fmaf(x.w, sWv[(f+3)*3+2], a2);
            }
            a0 += __shfl_xor_sync(0xffffffffu, a0, 1); a0 += __shfl_xor_sync(0xffffffffu, a0, 2);
            a1 += __shfl_xor_sync(0xffffffffu, a1, 1); a1 += __shfl_xor_sync(0xffffffffu, a1, 2);
            a2 += __shfl_xor_sync(0xffffffffu, a2, 1); a2 += __shfl_xor_sync(0xffffffffu, a2, 2);
            if ((tid & 3) == 0) {
                sVS[r*4 + 0] = a0; sVS[r*4 + 1] = a1; sVS[r*4 + 2] = a2;
            }
        }
        __syncthreads();
        for (int i = tid; i < 512; i += 256) {
            int p = i >> 3, g = i & 7;
            uint32_t w;
            if (g < 3)       w = pkbf(sVS[(2*p)*4 + g], sVS[(2*p+1)*4 + g]);
            else if (g == 3) w = 0x3F803F80u;       // {1.0bf, 1.0bf}
            else             w = 0u;
            g_vwp[(row0 >> 1)*8 + i] = w;
        }
    }
}

// ---------------------------------------------------------------------------
// Flash kernel: 256 threads (8 warps x 32 q-rows), q-tile 256, split-K 2-way.
// QK^T via bf16-split HMMA; softmax (no max) via ex2; PV via HMMA with
// pre-packed vwp B-fragments (col 3 = ones -> l accumulated by the MMA).
// ---------------------------------------------------------------------------
#define RSTRK 144
#define SQ_OFF 0
#define SK_OFF 32768                       // Q: 256*128
#define KTILEB (128*RSTRK)                 // 18432
#define VWP_OFF (SK_OFF + 2*KTILEB)        // 69632
#define VWPB 2048
#define SMEM_BYTES (VWP_OFF + 2*VWPB)      // 73728

__global__ __launch_bounds__(256, 3)
void flash8_kernel(void) {
    extern __shared__ __align__(16) unsigned char smem[];
    const int tid  = threadIdx.x;
    const int wid  = tid >> 5, lane = tid & 31;
    const size_t base = (size_t)blockIdx.y * SS;
    const int q0 = blockIdx.x * 256;
    const int z  = blockIdx.z;
    const uint32_t sbase = smem_u32(smem);

    // prologue: Q tile (group 0), first K tile + vwp (group 1)
    #pragma unroll
    for (int k = 0; k < 8; ++k) {
        int i = tid + k*256;
        cp16(sbase + SQ_OFF + i*16,
             (const unsigned char*)g_qp + (base + q0)*128 + i*16);
    }
    CP_COMMIT();
    {
        const size_t kb = base + (size_t)z * 1024;
        #pragma unroll
        for (int k = 0; k < 4; ++k) {
            int i = tid + k*256;
            int rr = i >> 3, sg = i & 7;
            cp16(sbase + SK_OFF + rr*RSTRK + sg*16,
                 (const unsigned char*)g_kp + (kb + rr)*128 + sg*16);
        }
        if (tid < 128)
            cp16(sbase + VWP_OFF + tid*16, g_vwp + (kb >> 1)*8 + tid*4);
    }
    CP_COMMIT();
    CP_WAIT(1);            // Q ready
    __syncthreads();

    const int lr  = lane & 7;
    const int sel = lane >> 3;

    // A fragments (loop-invariant): qh steps {0,1} then ql steps {0,1}
    uint32_t aF[2][4][4];
    #pragma unroll
    for (int mt = 0; mt < 2; ++mt) {
        int arow = wid*32 + mt*16 + lr + (sel & 1)*8;
        uint32_t abase = sbase + SQ_OFF + arow*128 + (sel >> 1)*16;
        #pragma unroll
        for (int g = 0; g < 4; ++g)
            LDSM_X4(aF[mt][g][0], aF[mt][g][1], aF[mt][g][2], aF[mt][g][3], abase + g*32);
    }

    // PV accumulators: d[mt][0..3]; cols 2t,2t+1 (t=lane&3):
    //   t=0 -> {A0,A1}, t=1 -> {A2,l}, t>=2 -> zeros
    float d[2][4];
    #pragma unroll
    for (int mt = 0; mt < 2; ++mt)
        #pragma unroll
        for (int i = 0; i < 4; ++i) d[mt][i] = 0.f;

    const int tq = lane & 3, gq = lane >> 2;

    #pragma unroll 1
    for (int ti = 0; ti < 8; ++ti) {
        if (ti < 7) {
            const size_t kb = base + (size_t)z*1024 + (size_t)(ti+1)*128;
            uint32_t db  = sbase + SK_OFF + ((ti+1) & 1)*KTILEB;
            uint32_t dvb = sbase + VWP_OFF + ((ti+1) & 1)*VWPB;
            #pragma unroll
            for (int k = 0; k < 4; ++k) {
                int i = tid + k*256;
                int rr = i >> 3, sg = i & 7;
                cp16(db + rr*RSTRK + sg*16,
                     (const unsigned char*)g_kp + (kb + rr)*128 + sg*16);
            }
            if (tid < 128)
                cp16(dvb + tid*16, g_vwp + (kb >> 1)*8 + tid*4);
            CP_COMMIT();
            CP_WAIT(1);
        } else {
            CP_WAIT(0);
        }
        __syncthreads();

        const uint32_t sk  = sbase + SK_OFF + (ti & 1)*KTILEB;
        const uint32_t svw = sbase + VWP_OFF + (ti & 1)*VWPB;

        #pragma unroll 2
        for (int jp = 0; jp < 8; ++jp) {
            // B fragments for QK (two n-tiles of the pair)
            uint32_t be[8], bo_[8];
            {
                uint32_t bb = sk + ((2*jp)*8 + lr)*RSTRK + sel*16;
                LDSM_X4(be[0], be[1], be[2], be[3], bb);
                LDSM_X4(be[4], be[5], be[6], be[7], bb + 64);
                uint32_t bb2 = sk + ((2*jp+1)*8 + lr)*RSTRK + sel*16;
                LDSM_X4(bo_[0], bo_[1], bo_[2], bo_[3], bb2);
                LDSM_X4(bo_[4], bo_[5], bo_[6], bo_[7], bb2 + 64);
            }
            // PV B fragments (pre-packed)
            uint32_t pb0, pb1;
            {
                uint32_t va0, va1;
                asm volatile("ld.shared.b32 %0, [%1];" : "=r"(va0)
                             : "r"(svw + ((jp*8 + tq)*8 + gq)*4));
                asm volatile("ld.shared.b32 %0, [%1];" : "=r"(va1)
                             : "r"(svw + ((jp*8 + 4 + tq)*8 + gq)*4));
                pb0 = va0; pb1 = va1;
            }

            #pragma unroll
            for (int mt = 0; mt < 2; ++mt) {
                float e0=0.f,e1=0.f,e2=0.f,e3=0.f;   // j even scores
                float o0=0.f,o1=0.f,o2=0.f,o3=0.f;   // j odd scores
                MMA16816(e0,e1,e2,e3, aF[mt][0][0],aF[mt][0][1],aF[mt][0][2],aF[mt][0][3], be[0],be[1]);
                MMA16816(o0,o1,o2,o3, aF[mt][0][0],aF[mt][0][1],aF[mt][0][2],aF[mt][0][3], bo_[0],bo_[1]);
                MMA16816(e0,e1,e2,e3, aF[mt][1][0],aF[mt][1][1],aF[mt][1][2],aF[mt][1][3], be[2],be[3]);
                MMA16816(o0,o1,o2,o3, aF[mt][1][0],aF[mt][1][1],aF[mt][1][2],aF[mt][1][3], bo_[2],bo_[3]);
                MMA16816(e0,e1,e2,e3, aF[mt][0][0],aF[mt][0][1],aF[mt][0][2],aF[mt][0][3], be[4],be[5]);
                MMA16816(o0,o1,o2,o3, aF[mt][0][0],aF[mt][0][1],aF[mt][0][2],aF[mt][0][3], bo_[4],bo_[5]);
                MMA16816(e0,e1,e2,e3, aF[mt][1][0],aF[mt][1][1],aF[mt][1][2],aF[mt][1][3], be[6],be[7]);
                MMA16816(o0,o1,o2,o3, aF[mt][1][0],aF[mt][1][1],aF[mt][1][2],aF[mt][1][3], bo_[6],bo_[7]);
                MMA16816(e0,e1,e2,e3, aF[mt][2][0],aF[mt][2][1],aF[mt][2][2],aF[mt][2][3], be[0],be[1]);
                MMA16816(o0,o1,o2,o3, aF[mt][2][0],aF[mt][2][1],aF[mt][2][2],aF[mt][2][3], bo_[0],bo_[1]);
                MMA16816(e0,e1,e2,e3, aF[mt][3][0],aF[mt][3][1],aF[mt][3][2],aF[mt][3][3], be[2],be[3]);
                MMA16816(o0,o1,o2,o3, aF[mt][3][0],aF[mt][3][1],aF[mt][3][2],aF[mt][3][3], bo_[2],bo_[3]);

                float p0 = ex2f(e0), p1 = ex2f(e1), p2 = ex2f(e2), p3 = ex2f(e3);
                float p4 = ex2f(o0), p5 = ex2f(o1), p6 = ex2f(o2), p7 = ex2f(o3);
                uint32_t a0 = pkbf(p0, p1);
                uint32_t a1 = pkbf(p2, p3);
                uint32_t a2 = pkbf(p4, p5);
                uint32_t a3 = pkbf(p6, p7);
                MMA16816(d[mt][0], d[mt][1], d[mt][2], d[mt][3],
                         a0, a1, a2, a3, pb0, pb1);
            }
        }
        __syncthreads();
    }

    // gather: t=0 lanes hold {A0,A1}; t=1 lanes hold {A2,l}; shuffle-combine
    #pragma unroll
    for (int mt = 0; mt < 2; ++mt) {
        float az_r0 = __shfl_xor_sync(0xffffffffu, d[mt][0], 1);  // from t^1
        float l_r0  = __shfl_xor_sync(0xffffffffu, d[mt][1], 1);
        float az_r1 = __shfl_xor_sync(0xffffffffu, d[mt][2], 1);
        float l_r1  = __shfl_xor_sync(0xffffffffu, d[mt][3], 1);
        if (tq == 0) {
            size_t r = base + q0 + wid*32 + mt*16 + gq;
            g_part[(size_t)z*NROWS + r]     = make_float4(l_r0, d[mt][0], d[mt][1], az_r0);
            g_part[(size_t)z*NROWS + r + 8] = make_float4(l_r1, d[mt][2], d[mt][3], az_r1);
        }
    }
}

// ---------------------------------------------------------------------------
// Finalize: combine 2 split-K partials, normalize, add constant.
// ---------------------------------------------------------------------------
__global__ __launch_bounds__(256) void finalize_kernel(
    float* __restrict__ out,
    const float* __restrict__ bv,
    const float* __restrict__ Wo,
    const float* __restrict__ bo) {
    __shared__ float sCST[3];
    const int tid = threadIdx.x;
    if (tid < 3) {
        float s = bo[tid];
        #pragma unroll
        for (int d = 0; d < DK; ++d) {
            float w = 0.f;
            #pragma unroll
            for (int h = 0; h < 16; ++h) w += Wo[(h*DK + d)*3 + tid];
            s = fmaf(bv[d], w, s);
        }
        sCST[tid] = s;
    }
    __syncthreads();
    size_t row = (size_t)blockIdx.x * 256 + tid;
    float4 p0 = g_part[row];
    float4 p1 = g_part[NROWS + row];
    float inv = 1.0f / (p0.x + p1.x);
    out[row*3 + 0] = fmaf(p0.y + p1.y, inv, sCST[0]);
    out[row*3 + 1] = fmaf(p0.z + p1.z, inv, sCST[1]);
    out[row*3 + 2] = fmaf(p0.w + p1.w, inv, sCST[2]);
}

extern "C" void kernel_launch(void* const* d_in, const int* in_sizes, int n_in,
                              void* d_out, int out_size) {
    const float* qin = (const float*)d_in[0];
    const float* kin = (const float*)d_in[1];
    const float* vin = (const float*)d_in[2];
    const float* Wq  = (const float*)d_in[3];
    const float* bq  = (const float*)d_in[4];
    const float* Wk  = (const float*)d_in[5];
    const float* bk  = (const float*)d_in[6];
    const float* Wv  = (const float*)d_in[7];
    const float* bv  = (const float*)d_in[8];
    const float* Wo  = (const float*)d_in[9];
    const float* bo  = (const float*)d_in[10];
    float* out = (float*)d_out;

    cudaFuncSetAttribute(flash8_kernel,
                         cudaFuncAttributeMaxDynamicSharedMemorySize, SMEM_BYTES);
    cudaFuncSetAttribute(proj6_kernel,
                         cudaFuncAttributeMaxDynamicSharedMemorySize, P6_SMEM);
    prep_kernel<<<1, 256>>>(Wq, Wk, Wv, Wo);
    proj6_kernel<<<dim3(NROWS/128, 3), 256, P6_SMEM>>>(qin, kin, vin, bq, bk);
    flash8_kernel<<<dim3(SS/256, BB, 2), 256, SMEM_BYTES>>>();
    finalize_kernel<<<NROWS/256, 256>>>(out, bv, Wo, bo);
}

// round 12
// speedup vs baseline: 1.4278x; 1.0820x over previous
#include <cuda_runtime.h>
#include <cuda_bf16.h>
#include <math.h>
#include <cstdint>

#define BB 32
#define SS 2048
#define FF 128
#define DK 32
#define NROWS (BB*SS)

// Packed projections, 64 bf16 per row (128B): [hi(32) | lo(32)]
// q pre-scaled by log2(e)/sqrt(32)  (scores in log2 domain -> ex2)
__device__ __nv_bfloat16 g_qp[NROWS*64];
__device__ __nv_bfloat16 g_kp[NROWS*64];
// PV B-operand, pre-packed bf16x2: per key-pair p, 8 cols g:
//   g<3: {lo=vw[2p][g], hi=vw[2p+1][g]}, g==3: {1,1}, g>3: 0
__device__ uint32_t g_vwp[(NROWS/2)*8];
__device__ float4 g_part[2*NROWS];         // split-K partials {l, A0, A1, A2}
// Pre-split W images (ldmatrix-ready): per phase 8704 bf16 = 4352 hi + 4352 lo,
// layout img[c*136 + f] (c = out col 0..31, f = 0..127, 8 pad per row)
__device__ __nv_bfloat16 g_wimg[2][8704];
__device__ float g_wveff[FF*3];            // Wv @ Wo_eff
__device__ float g_cst[3];                 // bo + bv . Wo_eff

static __device__ __forceinline__ uint32_t smem_u32(const void* p) {
    uint32_t a;
    asm("{ .reg .u64 t; cvta.to.shared.u64 t, %1; cvt.u32.u64 %0, t; }" : "=r"(a) : "l"(p));
    return a;
}
static __device__ __forceinline__ void cp16(uint32_t dst, const void* src) {
    asm volatile("cp.async.cg.shared.global [%0], [%1], 16;" :: "r"(dst), "l"(src) : "memory");
}
#define CP_COMMIT() asm volatile("cp.async.commit_group;" ::: "memory")
#define CP_WAIT(n)  asm volatile("cp.async.wait_group %0;" :: "n"(n) : "memory")

static __device__ __forceinline__ float ex2f(float x) {
    float y; asm("ex2.approx.f32 %0, %1;" : "=f"(y) : "f"(x)); return y;
}
// pack {lo, hi} floats -> bf16x2 (memory order: lo first)
static __device__ __forceinline__ uint32_t pkbf(float lo, float hi) {
    uint32_t r;
    asm("cvt.rn.bf16x2.f32 %0, %1, %2;" : "=r"(r) : "f"(hi), "f"(lo));
    return r;
}
// split a float2 into bf16x2 hi + bf16x2 lo words
static __device__ __forceinline__ void split2(float2 x, uint32_t& h, uint32_t& l) {
    h = pkbf(x.x, x.y);
    float f0 = __uint_as_float(h << 16);
    float f1 = __uint_as_float(h & 0xFFFF0000u);
    l = pkbf(x.x - f0, x.y - f1);
}

#define LDSM_X4(r0,r1,r2,r3,addr) \
    asm volatile("ldmatrix.sync.aligned.m8n8.x4.shared.b16 {%0,%1,%2,%3}, [%4];" \
        : "=r"(r0), "=r"(r1), "=r"(r2), "=r"(r3) : "r"(addr))

#define MMA16816(c0,c1,c2,c3,a0,a1,a2,a3,b0,b1) \
    asm volatile("mma.sync.aligned.m16n8k16.row.col.f32.bf16.bf16.f32 " \
        "{%0,%1,%2,%3}, {%4,%5,%6,%7}, {%8,%9}, {%0,%1,%2,%3};" \
        : "+f"(c0), "+f"(c1), "+f"(c2), "+f"(c3) \
        : "r"(a0), "r"(a1), "r"(a2), "r"(a3), "r"(b0), "r"(b1))

// ---------------------------------------------------------------------------
// Prep: split/transposed W images + Wv_eff + output constant (runs once).
// ---------------------------------------------------------------------------
__global__ __launch_bounds__(256) void prep_kernel(
    const float* __restrict__ Wq, const float* __restrict__ Wk,
    const float* __restrict__ Wv, const float* __restrict__ Wo,
    const float* __restrict__ bv, const float* __restrict__ bo) {
    __shared__ float sWoE[DK*3];
    const int tid = threadIdx.x;
    #pragma unroll
    for (int p = 0; p < 2; ++p) {
        const float* W = p ? Wk : Wq;
        __nv_bfloat16* img = g_wimg[p];
        int c = tid & 31, fg = tid >> 5;
        #pragma unroll
        for (int i = 0; i < 16; ++i) {
            int f = fg*16 + i;
            float w = W[f*32 + c];
            __nv_bfloat16 h = __float2bfloat16(w);
            img[c*136 + f]        = h;
            img[4352 + c*136 + f] = __float2bfloat16(w - __bfloat162float(h));
        }
    }
    if (tid < 96) {
        int d = tid / 3, f = tid - d*3;
        float s = 0.f;
        #pragma unroll
        for (int h = 0; h < 16; ++h) s += Wo[(h*DK + d)*3 + f];
        sWoE[tid] = s;
    }
    __syncthreads();
    for (int i = tid; i < FF*3; i += 256) {
        int r = i / 3, f = i - r*3;
        float s = 0.f;
        #pragma unroll
        for (int d = 0; d < DK; ++d) s = fmaf(Wv[r*DK + d], sWoE[d*3 + f], s);
        g_wveff[i] = s;
    }
    if (tid < 3) {
        float s = bo[tid];
        #pragma unroll
        for (int d = 0; d < DK; ++d) s = fmaf(bv[d], sWoE[d*3 + tid], s);
        g_cst[tid] = s;
    }
}

// ---------------------------------------------------------------------------
// Projection: grid (512, 3), 256 threads, 128 rows/block.
// Q/K: A built in registers from global INSIDE the k-group loop (low reg
// pressure -> 4 blocks/SM); B from the pre-split W image. 3-term bf16 split.
// V: 4 threads/row + quad reduce, emits packed g_vwp fragments.
// ---------------------------------------------------------------------------
#define P6_SMEM 17536

__global__ __launch_bounds__(256, 4) void proj6_kernel(
    const float* __restrict__ qin, const float* __restrict__ kin, const float* __restrict__ vin,
    const float* __restrict__ bq, const float* __restrict__ bk) {
    extern __shared__ __align__(16) unsigned char dsm[];
    const int tid  = threadIdx.x;
    const int wid  = tid >> 5, lane = tid & 31;
    const int phase = blockIdx.y;
    const size_t row0 = (size_t)blockIdx.x * 128;
    const uint32_t sb = smem_u32(dsm);

    if (phase < 2) {
        const float* in = phase ? kin : qin;
        const float* bb = phase ? bk : bq;
        __nv_bfloat16* gout = phase ? g_kp : g_qp;
        const float qs = phase ? 1.0f
                               : 0.17677669529663687f * 1.4426950408889634f;

        // stage pre-split W image (17408 B)
        for (int i = tid; i < 1088; i += 256)
            cp16(sb + i*16, (const unsigned char*)g_wimg[phase] + i*16);
        CP_COMMIT();
        CP_WAIT(0);
        __syncthreads();

        const int gq = lane >> 2, tq = lane & 3;
        const int lr = lane & 7, sel = lane >> 3;
        const float* rp0 = in + (row0 + wid*16 + gq)*128;
        const float* rp1 = rp0 + 8*128;

        float acc[4][4];
        #pragma unroll
        for (int nt = 0; nt < 4; ++nt)
            #pragma unroll
            for (int i = 0; i < 4; ++i) acc[nt][i] = 0.f;

        #pragma unroll
        for (int g2 = 0; g2 < 4; ++g2) {
            // A for k-groups 2*g2, 2*g2+1 (just-in-time, 16 live regs)
            uint32_t ah[2][4], al[2][4];
            #pragma unroll
            for (int gg = 0; gg < 2; ++gg) {
                int cb = (2*g2 + gg)*16 + tq*2;
                float2 x00 = *(const float2*)(rp0 + cb);
                float2 x10 = *(const float2*)(rp1 + cb);
                float2 x01 = *(const float2*)(rp0 + cb + 8);
                float2 x11 = *(const float2*)(rp1 + cb + 8);
                split2(x00, ah[gg][0], al[gg][0]);
                split2(x10, ah[gg][1], al[gg][1]);
                split2(x01, ah[gg][2], al[gg][2]);
                split2(x11, ah[gg][3], al[gg][3]);
            }
            #pragma unroll
            for (int nt = 0; nt < 4; ++nt) {
                uint32_t bwh = sb + (nt*8 + lr)*272 + sel*16 + g2*64;
                uint32_t bwl = bwh + 8704;
                uint32_t bh[4], bl[4];
                LDSM_X4(bh[0], bh[1], bh[2], bh[3], bwh);
                LDSM_X4(bl[0], bl[1], bl[2], bl[3], bwl);
                MMA16816(acc[nt][0],acc[nt][1],acc[nt][2],acc[nt][3],
                         ah[0][0],ah[0][1],ah[0][2],ah[0][3], bh[0],bh[1]); // xh.wh
                MMA16816(acc[nt][0],acc[nt][1],acc[nt][2],acc[nt][3],
                         ah[1][0],ah[1][1],ah[1][2],ah[1][3], bh[2],bh[3]);
                MMA16816(acc[nt][0],acc[nt][1],acc[nt][2],acc[nt][3],
                         ah[0][0],ah[0][1],ah[0][2],ah[0][3], bl[0],bl[1]); // xh.wl
                MMA16816(acc[nt][0],acc[nt][1],acc[nt][2],acc[nt][3],
                         ah[1][0],ah[1][1],ah[1][2],ah[1][3], bl[2],bl[3]);
                MMA16816(acc[nt][0],acc[nt][1],acc[nt][2],acc[nt][3],
                         al[0][0],al[0][1],al[0][2],al[0][3], bh[0],bh[1]); // xl.wh
                MMA16816(acc[nt][0],acc[nt][1],acc[nt][2],acc[nt][3],
                         al[1][0],al[1][1],al[1][2],al[1][3], bh[2],bh[3]);
            }
        }

        // epilogue: bias + scale, split hi/lo, packed u32 stores
        #pragma unroll
        for (int nt = 0; nt < 4; ++nt) {
            int colp = nt*8 + tq*2;
            float b0 = bb[colp], b1 = bb[colp+1];
            #pragma unroll
            for (int hf = 0; hf < 2; ++hf) {
                size_t rrow = row0 + wid*16 + gq + hf*8;
                float v0 = (acc[nt][hf*2+0] + b0) * qs;
                float v1 = (acc[nt][hf*2+1] + b1) * qs;
                uint32_t hp = pkbf(v0, v1);
                float h0 = __uint_as_float(hp << 16);
                float h1 = __uint_as_float(hp & 0xFFFF0000u);
                uint32_t lp = pkbf(v0 - h0, v1 - h1);
                *(uint32_t*)((unsigned char*)gout + rrow*128 + colp*2)      = hp;
                *(uint32_t*)((unsigned char*)gout + rrow*128 + 64 + colp*2) = lp;
            }
        }
    } else {
        // V: vw rows via 4 threads/row + quad reduce, then pack fragments
        float* sWv = (float*)dsm;                 // [384]
        float* sVS = (float*)(dsm + 1536);        // [128][4]
        for (int i = tid; i < 384; i += 256) sWv[i] = g_wveff[i];
        __syncthreads();
        #pragma unroll
        for (int it = 0; it < 2; ++it) {
            int r = it*64 + (tid >> 2);
            const float* rp = vin + (row0 + r)*128 + (tid & 3)*32;
            float a0 = 0.f, a1 = 0.f, a2 = 0.f;
            #pragma unroll
            for (int f4 = 0; f4 < 8; ++f4) {
                float4 x = ((const float4*)rp)[f4];
                int f = (tid & 3)*32 + f4*4;
                a0 = fmaf(x.x, sWv[(f+0)*3+0], a0); a1 = fmaf(x.x, sWv[(f+0)*3+1], a1); a2 = fmaf(x.x, sWv[(f+0)*3+2], a2);
                a0 = fmaf(x.y, sWv[(f+1)*3+0], a0); a1 = fmaf(x.y, sWv[(f+1)*3+1], a1); a2 = fmaf(x.y, sWv[(f+1)*3+2], a2);
                a0 = fmaf(x.z, sWv[(f+2)*3+0], a0); a1 = fmaf(x.z, sWv[(f+2)*3+1], a1); a2 = fmaf(x.z, sWv[(f+2)*3+2], a2);
                a0 = fmaf(x.w, sWv[(f+3)*3+0], a0); a1 = fmaf(x.w, sWv[(f+3)*3+1], a1); a2 = fmaf(x.w, sWv[(f+3)*3+2], a2);
            }
            a0 += __shfl_xor_sync(0xffffffffu, a0, 1); a0 += __shfl_xor_sync(0xffffffffu, a0, 2);
            a1 += __shfl_xor_sync(0xffffffffu, a1, 1); a1 += __shfl_xor_sync(0xffffffffu, a1, 2);
            a2 += __shfl_xor_sync(0xffffffffu, a2, 1); a2 += __shfl_xor_sync(0xffffffffu, a2, 2);
            if ((tid & 3) == 0) {
                sVS[r*4 + 0] = a0; sVS[r*4 + 1] = a1; sVS[r*4 + 2] = a2;
            }
        }
        __syncthreads();
        for (int i = tid; i < 512; i += 256) {
            int p = i >> 3, g = i & 7;
            uint32_t w;
            if (g < 3)       w = pkbf(sVS[(2*p)*4 + g], sVS[(2*p+1)*4 + g]);
            else if (g == 3) w = 0x3F803F80u;       // {1.0bf, 1.0bf}
            else             w = 0u;
            g_vwp[(row0 >> 1)*8 + i] = w;
        }
    }
}

// ---------------------------------------------------------------------------
// Flash kernel: 256 threads (8 warps x 16 q-rows), q-tile 128, split-K 2-way.
// Q staged in the K-ring smem (A-frags extracted to regs before overwrite):
// smem request only 40960 B -> 4 blocks/SM. QK^T bf16-split HMMA; ex2
// softmax (no max); PV via HMMA with pre-packed vwp fragments.
// ---------------------------------------------------------------------------
#define RSTRK 144
#define KTILEB (128*RSTRK)                 // 18432
#define RINGSTRIDE (KTILEB + 2048)         // 20480 (K tile + vwp)
#define SMEM_BYTES (2*RINGSTRIDE)          // 40960

__global__ __launch_bounds__(256, 4)
void flash9_kernel(void) {
    extern __shared__ __align__(16) unsigned char smem[];
    const int tid  = threadIdx.x;
    const int wid  = tid >> 5, lane = tid & 31;
    const size_t base = (size_t)blockIdx.y * SS;
    const int q0 = blockIdx.x * 128;
    const int z  = blockIdx.z;
    const uint32_t sbase = smem_u32(smem);

    // stage Q tile (128 rows x 128B = 16 KB) in the ring area
    #pragma unroll
    for (int k = 0; k < 4; ++k) {
        int i = tid + k*256;
        cp16(sbase + i*16, (const unsigned char*)g_qp + (base + q0)*128 + i*16);
    }
    CP_COMMIT();
    CP_WAIT(0);
    __syncthreads();

    const int lr  = lane & 7;
    const int sel = lane >> 3;

    // A fragments (loop-invariant): qh steps {0,1}, ql steps {0,1}
    uint32_t aF[4][4];
    {
        int arow = wid*16 + lr + (sel & 1)*8;
        uint32_t abase = sbase + arow*128 + (sel >> 1)*16;
        #pragma unroll
        for (int g = 0; g < 4; ++g)
            LDSM_X4(aF[g][0], aF[g][1], aF[g][2], aF[g][3], abase + g*32);
    }
    __syncthreads();   // all warps done reading Q region

    // prefetch K tile 0 + vwp into ring buffer 0 (overwrites Q staging)
    {
        const size_t kb = base + (size_t)z * 1024;
        #pragma unroll
        for (int k = 0; k < 4; ++k) {
            int i = tid + k*256;
            int rr = i >> 3, sg = i & 7;
            cp16(sbase + rr*RSTRK + sg*16,
                 (const unsigned char*)g_kp + (kb + rr)*128 + sg*16);
        }
        if (tid < 128)
            cp16(sbase + KTILEB + tid*16, g_vwp + (kb >> 1)*8 + tid*4);
    }
    CP_COMMIT();

    // PV accumulators: cols 2t,2t+1 (t=lane&3): t=0 -> {A0,A1}, t=1 -> {A2,l}
    float d[4] = {0.f, 0.f, 0.f, 0.f};
    const int tq = lane & 3, gq = lane >> 2;

    #pragma unroll 1
    for (int ti = 0; ti < 8; ++ti) {
        if (ti < 7) {
            const size_t kb = base + (size_t)z*1024 + (size_t)(ti+1)*128;
            uint32_t db = sbase + ((ti+1) & 1)*RINGSTRIDE;
            #pragma unroll
            for (int k = 0; k < 4; ++k) {
                int i = tid + k*256;
                int rr = i >> 3, sg = i & 7;
                cp16(db + rr*RSTRK + sg*16,
                     (const unsigned char*)g_kp + (kb + rr)*128 + sg*16);
            }
            if (tid < 128)
                cp16(db + KTILEB + tid*16, g_vwp + (kb >> 1)*8 + tid*4);
            CP_COMMIT();
            CP_WAIT(1);
        } else {
            CP_WAIT(0);
        }
        __syncthreads();

        const uint32_t sk  = sbase + (ti & 1)*RINGSTRIDE;
        const uint32_t svw = sk + KTILEB;

        #pragma unroll 2
        for (int jp = 0; jp < 8; ++jp) {
            uint32_t be[8], bo_[8];
            {
                uint32_t bb = sk + ((2*jp)*8 + lr)*RSTRK + sel*16;
                LDSM_X4(be[0], be[1], be[2], be[3], bb);
                LDSM_X4(be[4], be[5], be[6], be[7], bb + 64);
                uint32_t bb2 = sk + ((2*jp+1)*8 + lr)*RSTRK + sel*16;
                LDSM_X4(bo_[0], bo_[1], bo_[2], bo_[3], bb2);
                LDSM_X4(bo_[4], bo_[5], bo_[6], bo_[7], bb2 + 64);
            }
            uint32_t pb0, pb1;
            asm volatile("ld.shared.b32 %0, [%1];" : "=r"(pb0)
                         : "r"(svw + ((jp*8 + tq)*8 + gq)*4));
            asm volatile("ld.shared.b32 %0, [%1];" : "=r"(pb1)
                         : "r"(svw + ((jp*8 + 4 + tq)*8 + gq)*4));

            float e0=0.f,e1=0.f,e2=0.f,e3=0.f;   // j even scores
            float o0=0.f,o1=0.f,o2=0.f,o3=0.f;   // j odd scores
            MMA16816(e0,e1,e2,e3, aF[0][0],aF[0][1],aF[0][2],aF[0][3], be[0],be[1]);
            MMA16816(o0,o1,o2,o3, aF[0][0],aF[0][1],aF[0][2],aF[0][3], bo_[0],bo_[1]);
            MMA16816(e0,e1,e2,e3, aF[1][0],aF[1][1],aF[1][2],aF[1][3], be[2],be[3]);
            MMA16816(o0,o1,o2,o3, aF[1][0],aF[1][1],aF[1][2],aF[1][3], bo_[2],bo_[3]);
            MMA16816(e0,e1,e2,e3, aF[0][0],aF[0][1],aF[0][2],aF[0][3], be[4],be[5]);
            MMA16816(o0,o1,o2,o3, aF[0][0],aF[0][1],aF[0][2],aF[0][3], bo_[4],bo_[5]);
            MMA16816(e0,e1,e2,e3, aF[1][0],aF[1][1],aF[1][2],aF[1][3], be[6],be[7]);
            MMA16816(o0,o1,o2,o3, aF[1][0],aF[1][1],aF[1][2],aF[1][3], bo_[6],bo_[7]);
            MMA16816(e0,e1,e2,e3, aF[2][0],aF[2][1],aF[2][2],aF[2][3], be[0],be[1]);
            MMA16816(o0,o1,o2,o3, aF[2][0],aF[2][1],aF[2][2],aF[2][3], bo_[0],bo_[1]);
            MMA16816(e0,e1,e2,e3, aF[3][0],aF[3][1],aF[3][2],aF[3][3], be[2],be[3]);
            MMA16816(o0,o1,o2,o3, aF[3][0],aF[3][1],aF[3][2],aF[3][3], bo_[2],bo_[3]);

            float p0 = ex2f(e0), p1 = ex2f(e1), p2 = ex2f(e2), p3 = ex2f(e3);
            float p4 = ex2f(o0), p5 = ex2f(o1), p6 = ex2f(o2), p7 = ex2f(o3);
            uint32_t a0 = pkbf(p0, p1);
            uint32_t a1 = pkbf(p2, p3);
            uint32_t a2 = pkbf(p4, p5);
            uint32_t a3 = pkbf(p6, p7);
            MMA16816(d[0], d[1], d[2], d[3], a0, a1, a2, a3, pb0, pb1);
        }
        __syncthreads();
    }

    // gather: t=0 lanes hold {A0,A1}; t=1 lanes hold {A2,l}; shuffle-combine
    {
        float az_r0 = __shfl_xor_sync(0xffffffffu, d[0], 1);  // from t^1
        float l_r0  = __shfl_xor_sync(0xffffffffu, d[1], 1);
        float az_r1 = __shfl_xor_sync(0xffffffffu, d[2], 1);
        float l_r1  = __shfl_xor_sync(0xffffffffu, d[3], 1);
        if (tq == 0) {
            size_t r = base + q0 + wid*16 + gq;
            g_part[(size_t)z*NROWS + r]     = make_float4(l_r0, d[0], d[1], az_r0);
            g_part[(size_t)z*NROWS + r + 8] = make_float4(l_r1, d[2], d[3], az_r1);
        }
    }
}

// ---------------------------------------------------------------------------
// Finalize: combine 2 split-K partials, normalize, add precomputed constant.
// ---------------------------------------------------------------------------
__global__ __launch_bounds__(256) void finalize_kernel(float* __restrict__ out) {
    const int tid = threadIdx.x;
    const float c0 = g_cst[0], c1 = g_cst[1], c2 = g_cst[2];
    size_t row = (size_t)blockIdx.x * 256 + tid;
    float4 p0 = g_part[row];
    float4 p1 = g_part[NROWS + row];
    float inv = 1.0f / (p0.x + p1.x);
    out[row*3 + 0] = fmaf(p0.y + p1.y, inv, c0);
    out[row*3 + 1] = fmaf(p0.z + p1.z, inv, c1);
    out[row*3 + 2] = fmaf(p0.w + p1.w, inv, c2);
}

extern "C" void kernel_launch(void* const* d_in, const int* in_sizes, int n_in,
                              void* d_out, int out_size) {
    const float* qin = (const float*)d_in[0];
    const float* kin = (const float*)d_in[1];
    const float* vin = (const float*)d_in[2];
    const float* Wq  = (const float*)d_in[3];
    const float* bq  = (const float*)d_in[4];
    const float* Wk  = (const float*)d_in[5];
    const float* bk  = (const float*)d_in[6];
    const float* Wv  = (const float*)d_in[7];
    const float* bv  = (const float*)d_in[8];
    const float* Wo  = (const float*)d_in[9];
    const float* bo  = (const float*)d_in[10];
    float* out = (float*)d_out;

    cudaFuncSetAttribute(flash9_kernel,
                         cudaFuncAttributeMaxDynamicSharedMemorySize, SMEM_BYTES);
    cudaFuncSetAttribute(proj6_kernel,
                         cudaFuncAttributeMaxDynamicSharedMemorySize, P6_SMEM);
    prep_kernel<<<1, 256>>>(Wq, Wk, Wv, Wo, bv, bo);
    proj6_kernel<<<dim3(NROWS/128, 3), 256, P6_SMEM>>>(qin, kin, vin, bq, bk);
    flash9_kernel<<<dim3(SS/128, BB, 2), 256, SMEM_BYTES>>>();
    finalize_kernel<<<NROWS/256, 256>>>(out);
}